// round 5
// baseline (speedup 1.0000x reference)
#include <cuda_runtime.h>
#include <cuda_bf16.h>
#include <stdint.h>

// ---------------------------------------------------------------------------
// Problem constants
// ---------------------------------------------------------------------------
#define B_  8
#define T_  2048
#define C_  512
#define U_  512
#define NG  1536          // 3*U
#define KP  1024          // K per split (2*C, W=2 window)
#define MM  (B_ * T_)     // 16384
#define KTOT 3072         // 3 bf16 splits x 1024
#define NITER 96          // KTOT / BK

// GEMM tiling: CTA 256x128, warp 64x64 (8 warps: 4 along M x 2 along N)
#define BM 256
#define BN 128
#define BK 32             // bf16 per chunk (64B data/row)
#define LDR 80            // padded smem row bytes (64 data + 16 pad)
#define A_STAGE (BM * LDR)                 // 20480
#define B_STAGE (BN * LDR)                 // 10240
#define STAGE_BYTES (A_STAGE + B_STAGE)    // 30720
#define DEPTH 4
#define SMEM_REQ (DEPTH * STAGE_BYTES)     // 122880

// scan chunking
#define NCH 32
#define CL  (T_ / NCH)    // 64

// ---------------------------------------------------------------------------
// Device scratch (static, no runtime alloc)
// ---------------------------------------------------------------------------
__device__ float g_Z[(size_t)MM * U_];
__device__ float g_F[(size_t)MM * U_];
__device__ float g_O[(size_t)MM * U_];
__device__ __nv_bfloat16 g_Xh[(size_t)MM * C_];
__device__ __nv_bfloat16 g_Xl[(size_t)MM * C_];
__device__ __nv_bfloat16 g_WhT[(size_t)NG * KP];
__device__ __nv_bfloat16 g_WlT[(size_t)NG * KP];
__device__ float g_cH[B_ * NCH * U_];
__device__ float g_cP[B_ * NCH * U_];
__device__ float g_Hin[B_ * NCH * U_];

// ---------------------------------------------------------------------------
// Helpers
// ---------------------------------------------------------------------------
__device__ __forceinline__ uint32_t smem_u32(const void* p) {
    uint32_t a;
    asm("{ .reg .u64 t; cvta.to.shared.u64 t, %1; cvt.u32.u64 %0, t; }"
        : "=r"(a) : "l"(p));
    return a;
}

#define CP16P(saddr, gptr, sz) \
    asm volatile("cp.async.cg.shared.global [%0], [%1], 16, %2;" \
                 :: "r"(saddr), "l"(gptr), "r"(sz))
#define CP_COMMIT() asm volatile("cp.async.commit_group;")
#define CP_WAIT2()  asm volatile("cp.async.wait_group 2;")

#define LDSM_X4(r0, r1, r2, r3, addr) \
    asm volatile("ldmatrix.sync.aligned.m8n8.x4.shared.b16 {%0,%1,%2,%3}, [%4];" \
                 : "=r"(r0), "=r"(r1), "=r"(r2), "=r"(r3) : "r"(addr))

#define MMA16816(d, a, b0, b1) \
    asm volatile("mma.sync.aligned.m16n8k16.row.col.f32.bf16.bf16.f32 " \
                 "{%0,%1,%2,%3}, {%4,%5,%6,%7}, {%8,%9}, {%0,%1,%2,%3};" \
                 : "+f"((d)[0]), "+f"((d)[1]), "+f"((d)[2]), "+f"((d)[3]) \
                 : "r"((a)[0]), "r"((a)[1]), "r"((a)[2]), "r"((a)[3]), \
                   "r"(b0), "r"(b1))

__device__ __forceinline__ float tanh_fast(float x) {
    float r; asm("tanh.approx.f32 %0, %1;" : "=f"(r) : "f"(x)); return r;
}
__device__ __forceinline__ float sig_fast(float x) {
    float e; asm("ex2.approx.f32 %0, %1;" : "=f"(e) : "f"(-x * 1.4426950408889634f));
    float r; asm("rcp.approx.f32 %0, %1;" : "=f"(r) : "f"(1.0f + e)); return r;
}

// ---------------------------------------------------------------------------
// prep_x: split fp32 x into bf16 hi + bf16 residual lo (elementwise)
// ---------------------------------------------------------------------------
__global__ __launch_bounds__(256) void prep_x(const float* __restrict__ x) {
    size_t g = (size_t)blockIdx.x * 256 + threadIdx.x;   // MM*C/4 threads
    float4 v = ((const float4*)x)[g];
    __nv_bfloat16 h0 = __float2bfloat16(v.x);
    __nv_bfloat16 h1 = __float2bfloat16(v.y);
    __nv_bfloat16 h2 = __float2bfloat16(v.z);
    __nv_bfloat16 h3 = __float2bfloat16(v.w);
    __nv_bfloat162 ha; ha.x = h0; ha.y = h1;
    __nv_bfloat162 hb; hb.x = h2; hb.y = h3;
    __nv_bfloat162 la; la.x = __float2bfloat16(v.x - __bfloat162float(h0));
    la.y = __float2bfloat16(v.y - __bfloat162float(h1));
    __nv_bfloat162 lb; lb.x = __float2bfloat16(v.z - __bfloat162float(h2));
    lb.y = __float2bfloat16(v.w - __bfloat162float(h3));
    ((__nv_bfloat162*)g_Xh)[g * 2]     = ha;
    ((__nv_bfloat162*)g_Xh)[g * 2 + 1] = hb;
    ((__nv_bfloat162*)g_Xl)[g * 2]     = la;
    ((__nv_bfloat162*)g_Xl)[g * 2 + 1] = lb;
}

// prep_w: transpose + split kernel[k,n] -> WhT/WlT[n,k]
__global__ void prep_w(const float* __restrict__ kern) {
    __shared__ __nv_bfloat16 sh[32][33];
    __shared__ __nv_bfloat16 sl[32][33];
    int k = blockIdx.y * 32 + threadIdx.y;
    int n = blockIdx.x * 32 + threadIdx.x;
    float v = kern[(size_t)k * NG + n];
    __nv_bfloat16 hi = __float2bfloat16(v);
    sh[threadIdx.y][threadIdx.x] = hi;
    sl[threadIdx.y][threadIdx.x] = __float2bfloat16(v - __bfloat162float(hi));
    __syncthreads();
    int nn = blockIdx.x * 32 + threadIdx.y;
    int kk = blockIdx.y * 32 + threadIdx.x;
    g_WhT[(size_t)nn * KP + kk] = sh[threadIdx.x][threadIdx.y];
    g_WlT[(size_t)nn * KP + kk] = sl[threadIdx.x][threadIdx.y];
}

// ---------------------------------------------------------------------------
// GEMM: gates[16384, 1536] = A[16384, 3072] @ Wcat[3072, 1536] via mma.sync
// A row m, split s, k: source Xs[m + w - 1, c]  (w=k/512, c=k%512),
// zero row when (w==0 && m%2048==0). Fused bias + activation epilogue.
// ---------------------------------------------------------------------------
__global__ __launch_bounds__(256, 1) void mma_gates(const float* __restrict__ bias) {
    extern __shared__ char smem[];
    const uint32_t sbase = smem_u32(smem);

    const int tid = threadIdx.x;
    const int wid = tid >> 5;
    const int lane = tid & 31;
    const int n0 = blockIdx.x * BN;
    const int m0 = blockIdx.y * BM;

    const int wm = (wid & 3) * 64;      // warp m offset (4 warps along M)
    const int wn = (wid >> 2) * 64;     // warp n offset (2 warps along N)

    const __nv_bfloat16* const Asrc[3] = { g_Xh, g_Xh, g_Xl };
    const __nv_bfloat16* const Bsrc[3] = { g_WhT, g_WlT, g_WhT };

    // cp.async: 1536 16B-chunks per stage / 256 threads = 6 per thread
    //   A rows rowq + {0,64,128,192}, B rows rowq + {0,64}
    const int rowq = tid >> 2;          // 0..63
    const int jq   = tid & 3;           // chunk-in-row

#define LOAD_STAGE(cc) do { \
    const int _c = (cc); \
    const int _s = _c >> 5; \
    const int _kb = (_c & 31) * BK; \
    const __nv_bfloat16* _Ap = Asrc[_s]; \
    const __nv_bfloat16* _Bp = Bsrc[_s]; \
    const uint32_t _st = sbase + (uint32_t)(_c % DEPTH) * STAGE_BYTES; \
    const int _k = _kb + jq * 8; \
    const int _w = _k >> 9; \
    const int _cc2 = _k & 511; \
    _Pragma("unroll") \
    for (int _i = 0; _i < 4; _i++) { \
        int _row = rowq + _i * 64; \
        int _m = m0 + _row; \
        int _r = _m + _w - 1; \
        uint32_t _sz = (_w == 0 && (_m & (T_ - 1)) == 0) ? 0u : 16u; \
        if (_sz == 0u) _r = _m; \
        const void* _gp = _Ap + (size_t)_r * C_ + _cc2; \
        CP16P(_st + (uint32_t)(_row * LDR + jq * 16), _gp, _sz); \
    } \
    _Pragma("unroll") \
    for (int _i = 0; _i < 2; _i++) { \
        int _row = rowq + _i * 64; \
        const void* _gp = _Bp + (size_t)(n0 + _row) * KP + _kb + jq * 8; \
        CP16P(_st + (uint32_t)(A_STAGE + _row * LDR + jq * 16), _gp, 16u); \
    } \
    CP_COMMIT(); \
} while (0)

    float acc[4][8][4];
#pragma unroll
    for (int mt = 0; mt < 4; mt++)
#pragma unroll
        for (int nt = 0; nt < 8; nt++)
#pragma unroll
            for (int r = 0; r < 4; r++) acc[mt][nt][r] = 0.0f;

    LOAD_STAGE(0);
    LOAD_STAGE(1);
    LOAD_STAGE(2);

    // ldmatrix lane address components (fixed per thread)
    const int a_row = lane & 15;             // row within m16 tile
    const int a_chk = lane >> 4;             // 0/1 -> k-half select
    const int b_row = (lane & 7) + ((lane >> 4) << 3);  // n row within pair
    const int b_chk = (lane >> 3) & 1;       // k-half select

#pragma unroll 1
    for (int cc = 0; cc < NITER; cc++) {
        CP_WAIT2();
        __syncthreads();
        if (cc + 3 < NITER) {
            LOAD_STAGE(cc + 3);
        } else {
            CP_COMMIT();
        }

        const uint32_t st = sbase + (uint32_t)(cc % DEPTH) * STAGE_BYTES;
        const uint32_t sA = st + (uint32_t)((wm + a_row) * LDR);
        const uint32_t sB = st + (uint32_t)(A_STAGE + (wn + b_row) * LDR);

#pragma unroll
        for (int ks = 0; ks < 2; ks++) {
            uint32_t a[4][4];
            uint32_t b[4][4];
#pragma unroll
            for (int mt = 0; mt < 4; mt++) {
                uint32_t ad = sA + (uint32_t)(mt * 16 * LDR + (a_chk + ks * 2) * 16);
                LDSM_X4(a[mt][0], a[mt][1], a[mt][2], a[mt][3], ad);
            }
#pragma unroll
            for (int p = 0; p < 4; p++) {
                uint32_t bd = sB + (uint32_t)(p * 16 * LDR + (b_chk + ks * 2) * 16);
                LDSM_X4(b[p][0], b[p][1], b[p][2], b[p][3], bd);
            }
#pragma unroll
            for (int mt = 0; mt < 4; mt++)
#pragma unroll
                for (int p = 0; p < 4; p++) {
                    MMA16816(acc[mt][2 * p],     a[mt], b[p][0], b[p][1]);
                    MMA16816(acc[mt][2 * p + 1], a[mt], b[p][2], b[p][3]);
                }
        }
    }

    // ---- epilogue: bias + activation + store, straight from registers ----
    const int ng = n0 + wn;                   // warp n base (global)
    const int gate = ng >> 9;                 // 0:z 1:f 2:o
    float* dst = (gate == 0) ? g_Z : ((gate == 1) ? g_F : g_O);
    const int colw = (ng & 511) + (lane & 3) * 2;

    float bs0[8], bs1[8];
#pragma unroll
    for (int nt = 0; nt < 8; nt++) {
        bs0[nt] = __ldg(bias + ng + (lane & 3) * 2 + nt * 8);
        bs1[nt] = __ldg(bias + ng + (lane & 3) * 2 + nt * 8 + 1);
    }

#pragma unroll
    for (int mt = 0; mt < 4; mt++) {
        int row = m0 + wm + mt * 16 + (lane >> 2);
        float* p0 = dst + (size_t)row * U_;
        float* p1 = dst + (size_t)(row + 8) * U_;
#pragma unroll
        for (int nt = 0; nt < 8; nt++) {
            int col = colw + nt * 8;
            float g0 = acc[mt][nt][0] + bs0[nt];
            float g1 = acc[mt][nt][1] + bs1[nt];
            float g2 = acc[mt][nt][2] + bs0[nt];
            float g3 = acc[mt][nt][3] + bs1[nt];
            float2 v0, v1;
            if (gate == 0) {
                v0.x = tanh_fast(g0); v0.y = tanh_fast(g1);
                v1.x = tanh_fast(g2); v1.y = tanh_fast(g3);
            } else {
                v0.x = sig_fast(g0); v0.y = sig_fast(g1);
                v1.x = sig_fast(g2); v1.y = sig_fast(g3);
            }
            *(float2*)(p0 + col) = v0;
            *(float2*)(p1 + col) = v1;
        }
    }
}

// ---------------------------------------------------------------------------
// Chunked fo-pool scan (h affine in h_in: h = P*h_in + H), float4 vectorized
// ---------------------------------------------------------------------------
__global__ __launch_bounds__(256) void scan_pass1() {
    int id = blockIdx.x * 256 + threadIdx.x;       // B*NCH*U/4 = 32768
    int u4 = id & 127;                             // 4-wide u group
    int ch = (id >> 7) & (NCH - 1);
    int b  = id >> 12;
    size_t base4 = (((size_t)b * T_ + (size_t)ch * CL) * U_ + u4 * 4) >> 2;
    const float4* F4 = (const float4*)g_F;
    const float4* Z4 = (const float4*)g_Z;
    float4 h = make_float4(0.f, 0.f, 0.f, 0.f);
    float4 P = make_float4(1.f, 1.f, 1.f, 1.f);
#pragma unroll 4
    for (int t = 0; t < CL; t++) {
        float4 f = F4[base4 + (size_t)t * (U_ / 4)];
        float4 z = Z4[base4 + (size_t)t * (U_ / 4)];
        h.x = fmaf(f.x, h.x - z.x, z.x); P.x *= f.x;
        h.y = fmaf(f.y, h.y - z.y, z.y); P.y *= f.y;
        h.z = fmaf(f.z, h.z - z.z, z.z); P.z *= f.z;
        h.w = fmaf(f.w, h.w - z.w, z.w); P.w *= f.w;
    }
    size_t o4 = ((size_t)(b * NCH + ch) * U_ + u4 * 4) >> 2;
    ((float4*)g_cH)[o4] = h;
    ((float4*)g_cP)[o4] = P;
}

__global__ __launch_bounds__(512) void scan_pass2(const float* __restrict__ init) {
    int id = blockIdx.x * 512 + threadIdx.x;       // 4096 = B*U
    int u = id & 511;
    int b = id >> 9;
    float h = init[u];
#pragma unroll
    for (int c = 0; c < NCH; c++) {
        int o = (b * NCH + c) * U_ + u;
        g_Hin[o] = h;
        h = fmaf(g_cP[o], h, g_cH[o]);
    }
}

__global__ __launch_bounds__(256) void scan_pass3(float* __restrict__ out) {
    int id = blockIdx.x * 256 + threadIdx.x;       // 32768
    int u4 = id & 127;
    int ch = (id >> 7) & (NCH - 1);
    int b  = id >> 12;
    size_t base4 = (((size_t)b * T_ + (size_t)ch * CL) * U_ + u4 * 4) >> 2;
    const float4* F4 = (const float4*)g_F;
    const float4* Z4 = (const float4*)g_Z;
    const float4* O4 = (const float4*)g_O;
    float4* out4 = (float4*)out;
    float4 h = ((const float4*)g_Hin)[((size_t)(b * NCH + ch) * U_ + u4 * 4) >> 2];
#pragma unroll 4
    for (int t = 0; t < CL; t++) {
        size_t idx = base4 + (size_t)t * (U_ / 4);
        float4 f = F4[idx];
        float4 z = Z4[idx];
        float4 o = O4[idx];
        float4 r;
        h.x = fmaf(f.x, h.x - z.x, z.x); r.x = h.x * o.x;
        h.y = fmaf(f.y, h.y - z.y, z.y); r.y = h.y * o.y;
        h.z = fmaf(f.z, h.z - z.z, z.z); r.z = h.z * o.z;
        h.w = fmaf(f.w, h.w - z.w, z.w); r.w = h.w * o.w;
        out4[idx] = r;
    }
}

// ---------------------------------------------------------------------------
extern "C" void kernel_launch(void* const* d_in, const int* in_sizes, int n_in,
                              void* d_out, int out_size)
{
    const float* x    = (const float*)d_in[0];  // [8,2048,512]
    const float* kern = (const float*)d_in[1];  // [2,512,1536]
    const float* bias = (const float*)d_in[2];  // [1536]
    const float* init = (const float*)d_in[3];  // [1,512]
    float* out = (float*)d_out;                 // [8,2048,512]

    cudaFuncSetAttribute(mma_gates, cudaFuncAttributeMaxDynamicSharedMemorySize, SMEM_REQ);

    prep_x<<<(MM * C_) / (256 * 4), 256>>>(x);
    prep_w<<<dim3(NG / 32, KP / 32), dim3(32, 32)>>>(kern);
    mma_gates<<<dim3(NG / BN, MM / BM), 256, SMEM_REQ>>>(bias);
    scan_pass1<<<(B_ * NCH * U_) / (256 * 4), 256>>>();
    scan_pass2<<<(B_ * U_) / 512, 512>>>(init);
    scan_pass3<<<(B_ * NCH * U_) / (256 * 4), 256>>>(out);
}

// round 7
// speedup vs baseline: 1.4924x; 1.4924x over previous
#include <cuda_runtime.h>
#include <cuda_fp16.h>
#include <stdint.h>

// ---------------------------------------------------------------------------
// Problem constants
// ---------------------------------------------------------------------------
#define B_  8
#define T_  2048
#define C_  512
#define U_  512
#define NG  1536          // 3*U
#define KP  1024          // K per split (2*C, W=2 window)
#define MM  (B_ * T_)     // 16384
#define NITER 64          // 2 splits * (1024/32)

// GEMM tiling (round-3 proven config): CTA 256x128, warp 32x64, 512 threads
#define BM 256
#define BN 128
#define BK 32             // fp16 per chunk (64B data/row)
#define LDR 80            // padded smem row bytes (64 data + 16 pad)
#define A_STAGE (BM * LDR)                 // 20480
#define B_STAGE (BN * LDR)                 // 10240
#define STAGE_BYTES (A_STAGE + B_STAGE)    // 30720
#define DEPTH 3
#define SMEM_REQ (DEPTH * STAGE_BYTES)     // 92160

// scan chunking
#define NCH 32
#define CL  (T_ / NCH)    // 64

// ---------------------------------------------------------------------------
// Device scratch (static, no runtime alloc)
// ---------------------------------------------------------------------------
__device__ float g_Z[(size_t)MM * U_];
__device__ float g_F[(size_t)MM * U_];
__device__ float g_O[(size_t)MM * U_];
__device__ __half g_X16[(size_t)MM * C_];
__device__ __half g_WhT[(size_t)NG * KP];
__device__ __half g_WlT[(size_t)NG * KP];
__device__ float g_cH[B_ * NCH * U_];
__device__ float g_cP[B_ * NCH * U_];
__device__ float g_Hin[B_ * NCH * U_];

// ---------------------------------------------------------------------------
// Helpers
// ---------------------------------------------------------------------------
__device__ __forceinline__ uint32_t smem_u32(const void* p) {
    uint32_t a;
    asm("{ .reg .u64 t; cvta.to.shared.u64 t, %1; cvt.u32.u64 %0, t; }"
        : "=r"(a) : "l"(p));
    return a;
}

#define CP16P(saddr, gptr, sz) \
    asm volatile("cp.async.cg.shared.global [%0], [%1], 16, %2;" \
                 :: "r"(saddr), "l"(gptr), "r"(sz))
#define CP_COMMIT() asm volatile("cp.async.commit_group;")
#define CP_WAIT1()  asm volatile("cp.async.wait_group 1;")

#define LDSM_X4(r0, r1, r2, r3, addr) \
    asm volatile("ldmatrix.sync.aligned.m8n8.x4.shared.b16 {%0,%1,%2,%3}, [%4];" \
                 : "=r"(r0), "=r"(r1), "=r"(r2), "=r"(r3) : "r"(addr))

#define MMA16816(d, a, b0, b1) \
    asm volatile("mma.sync.aligned.m16n8k16.row.col.f32.f16.f16.f32 " \
                 "{%0,%1,%2,%3}, {%4,%5,%6,%7}, {%8,%9}, {%0,%1,%2,%3};" \
                 : "+f"((d)[0]), "+f"((d)[1]), "+f"((d)[2]), "+f"((d)[3]) \
                 : "r"((a)[0]), "r"((a)[1]), "r"((a)[2]), "r"((a)[3]), \
                   "r"(b0), "r"(b1))

__device__ __forceinline__ float tanh_fast(float x) {
    float r; asm("tanh.approx.f32 %0, %1;" : "=f"(r) : "f"(x)); return r;
}
__device__ __forceinline__ float sig_fast(float x) {
    float e; asm("ex2.approx.f32 %0, %1;" : "=f"(e) : "f"(-x * 1.4426950408889634f));
    float r; asm("rcp.approx.f32 %0, %1;" : "=f"(r) : "f"(1.0f + e)); return r;
}

// ---------------------------------------------------------------------------
// prep_x: fp32 x -> single fp16
// ---------------------------------------------------------------------------
__global__ __launch_bounds__(256) void prep_x(const float* __restrict__ x) {
    size_t g = (size_t)blockIdx.x * 256 + threadIdx.x;   // MM*C/4 threads
    float4 v = ((const float4*)x)[g];
    __half2 a; a.x = __float2half(v.x); a.y = __float2half(v.y);
    __half2 b; b.x = __float2half(v.z); b.y = __float2half(v.w);
    ((__half2*)g_X16)[g * 2]     = a;
    ((__half2*)g_X16)[g * 2 + 1] = b;
}

// prep_w: transpose + fp16 hi/lo split: kern[k,n] -> WhT/WlT[n,k]
__global__ void prep_w(const float* __restrict__ kern) {
    __shared__ __half sh[32][33];
    __shared__ __half sl[32][33];
    int k = blockIdx.y * 32 + threadIdx.y;
    int n = blockIdx.x * 32 + threadIdx.x;
    float v = kern[(size_t)k * NG + n];
    __half hi = __float2half(v);
    sh[threadIdx.y][threadIdx.x] = hi;
    sl[threadIdx.y][threadIdx.x] = __float2half(v - __half2float(hi));
    __syncthreads();
    int nn = blockIdx.x * 32 + threadIdx.y;
    int kk = blockIdx.y * 32 + threadIdx.x;
    g_WhT[(size_t)nn * KP + kk] = sh[threadIdx.x][threadIdx.y];
    g_WlT[(size_t)nn * KP + kk] = sl[threadIdx.x][threadIdx.y];
}

// ---------------------------------------------------------------------------
// GEMM: gates[16384,1536] = A16[16384,1024] @ (WhT + WlT), 2 K-passes.
// A row m, k: source X16[m + w - 1, c]  (w=k/512, c=k%512),
// zero row when (w==0 && m%2048==0). Fused bias + activation epilogue.
// ---------------------------------------------------------------------------
__global__ __launch_bounds__(512) void mma_gates(const float* __restrict__ bias) {
    extern __shared__ char smem[];
    const uint32_t sbase = smem_u32(smem);

    const int tid = threadIdx.x;
    const int wid = tid >> 5;
    const int lane = tid & 31;
    const int n0 = blockIdx.x * BN;
    const int m0 = blockIdx.y * BM;

    const int wm = (wid & 7) * 32;      // warp m offset (8 warps along M)
    const int wn = (wid >> 3) * 64;     // warp n offset (2 warps along N)

    const __half* const Bsrc[2] = { g_WhT, g_WlT };

    // cp.async: 1536 16B-chunks per stage / 512 threads = 3 per thread
    const int rowq = tid >> 2;          // 0..127
    const int jq   = tid & 3;           // chunk-in-row

#define LOAD_STAGE(cc) do { \
    const int _c = (cc); \
    const int _s = _c >> 5; \
    const int _kb = (_c & 31) * BK; \
    const __half* _Bp = Bsrc[_s]; \
    const uint32_t _st = sbase + (uint32_t)(_c % DEPTH) * STAGE_BYTES; \
    const int _k = _kb + jq * 8; \
    const int _w = _k >> 9; \
    const int _cc2 = _k & 511; \
    _Pragma("unroll") \
    for (int _i = 0; _i < 2; _i++) { \
        int _row = rowq + _i * 128; \
        int _m = m0 + _row; \
        int _r = _m + _w - 1; \
        uint32_t _sz = (_w == 0 && (_m & (T_ - 1)) == 0) ? 0u : 16u; \
        if (_sz == 0u) _r = _m; \
        const void* _gp = g_X16 + (size_t)_r * C_ + _cc2; \
        CP16P(_st + (uint32_t)(_row * LDR + jq * 16), _gp, _sz); \
    } \
    { \
        const void* _gp = _Bp + (size_t)(n0 + rowq) * KP + _kb + jq * 8; \
        CP16P(_st + (uint32_t)(A_STAGE + rowq * LDR + jq * 16), _gp, 16u); \
    } \
    CP_COMMIT(); \
} while (0)

    float acc[2][8][4];
#pragma unroll
    for (int mt = 0; mt < 2; mt++)
#pragma unroll
        for (int nt = 0; nt < 8; nt++)
#pragma unroll
            for (int r = 0; r < 4; r++) acc[mt][nt][r] = 0.0f;

    LOAD_STAGE(0);
    LOAD_STAGE(1);

    // ldmatrix lane address components (fixed per thread)
    const int a_row = lane & 15;             // row within m16 tile
    const int a_chk = lane >> 4;             // 0/1 -> k-half
    const int b_row = (lane & 7) + ((lane >> 4) << 3);  // n row within pair
    const int b_chk = (lane >> 3) & 1;       // k-half select

#pragma unroll 1
    for (int cc = 0; cc < NITER; cc++) {
        CP_WAIT1();
        __syncthreads();
        if (cc + 2 < NITER) {
            LOAD_STAGE(cc + 2);
        } else {
            CP_COMMIT();
        }

        const uint32_t st = sbase + (uint32_t)(cc % DEPTH) * STAGE_BYTES;
        const uint32_t sA = st + (uint32_t)((wm + a_row) * LDR);
        const uint32_t sB = st + (uint32_t)(A_STAGE + (wn + b_row) * LDR);

#pragma unroll
        for (int ks = 0; ks < 2; ks++) {
            uint32_t a[2][4];
            uint32_t b[4][4];
#pragma unroll
            for (int mt = 0; mt < 2; mt++) {
                uint32_t ad = sA + (uint32_t)(mt * 16 * LDR + (a_chk + ks * 2) * 16);
                LDSM_X4(a[mt][0], a[mt][1], a[mt][2], a[mt][3], ad);
            }
#pragma unroll
            for (int p = 0; p < 4; p++) {
                uint32_t bd = sB + (uint32_t)(p * 16 * LDR + (b_chk + ks * 2) * 16);
                LDSM_X4(b[p][0], b[p][1], b[p][2], b[p][3], bd);
            }
#pragma unroll
            for (int mt = 0; mt < 2; mt++)
#pragma unroll
                for (int p = 0; p < 4; p++) {
                    MMA16816(acc[mt][2 * p],     a[mt], b[p][0], b[p][1]);
                    MMA16816(acc[mt][2 * p + 1], a[mt], b[p][2], b[p][3]);
                }
        }
    }

    // ---- epilogue: bias + activation + store, straight from registers ----
    const int ng = n0 + wn;                   // warp n base (global)
    const int gate = ng >> 9;                 // 0:z 1:f 2:o
    float* dst = (gate == 0) ? g_Z : ((gate == 1) ? g_F : g_O);
    const int colw = (ng & 511) + (lane & 3) * 2;

    float bs0[8], bs1[8];
#pragma unroll
    for (int nt = 0; nt < 8; nt++) {
        bs0[nt] = __ldg(bias + ng + (lane & 3) * 2 + nt * 8);
        bs1[nt] = __ldg(bias + ng + (lane & 3) * 2 + nt * 8 + 1);
    }

#pragma unroll
    for (int mt = 0; mt < 2; mt++) {
        int row = m0 + wm + mt * 16 + (lane >> 2);
        float* p0 = dst + (size_t)row * U_;
        float* p1 = dst + (size_t)(row + 8) * U_;
#pragma unroll
        for (int nt = 0; nt < 8; nt++) {
            int col = colw + nt * 8;
            float g0 = acc[mt][nt][0] + bs0[nt];
            float g1 = acc[mt][nt][1] + bs1[nt];
            float g2 = acc[mt][nt][2] + bs0[nt];
            float g3 = acc[mt][nt][3] + bs1[nt];
            float2 v0, v1;
            if (gate == 0) {
                v0.x = tanh_fast(g0); v0.y = tanh_fast(g1);
                v1.x = tanh_fast(g2); v1.y = tanh_fast(g3);
            } else {
                v0.x = sig_fast(g0); v0.y = sig_fast(g1);
                v1.x = sig_fast(g2); v1.y = sig_fast(g3);
            }
            *(float2*)(p0 + col) = v0;
            *(float2*)(p1 + col) = v1;
        }
    }
}

// ---------------------------------------------------------------------------
// Chunked fo-pool scan (h affine in h_in: h = P*h_in + H) — scalar (round 3)
// ---------------------------------------------------------------------------
__global__ __launch_bounds__(256) void scan_pass1() {
    int id = blockIdx.x * 256 + threadIdx.x;       // B*NCH*U = 131072
    int u = id & 511;
    int ch = (id >> 9) & (NCH - 1);
    int b = id >> 14;
    size_t base = ((size_t)b * T_ + (size_t)ch * CL) * U_ + u;
    float h = 0.0f, P = 1.0f;
#pragma unroll 8
    for (int t = 0; t < CL; t++) {
        float f = g_F[base + (size_t)t * U_];
        float z = g_Z[base + (size_t)t * U_];
        h = fmaf(f, h - z, z);
        P *= f;
    }
    int o = (b * NCH + ch) * U_ + u;
    g_cH[o] = h;
    g_cP[o] = P;
}

__global__ __launch_bounds__(512) void scan_pass2(const float* __restrict__ init) {
    int id = blockIdx.x * 512 + threadIdx.x;       // 4096 = B*U
    int u = id & 511;
    int b = id >> 9;
    float h = init[u];
#pragma unroll
    for (int c = 0; c < NCH; c++) {
        int o = (b * NCH + c) * U_ + u;
        g_Hin[o] = h;
        h = fmaf(g_cP[o], h, g_cH[o]);
    }
}

__global__ __launch_bounds__(256) void scan_pass3(float* __restrict__ out) {
    int id = blockIdx.x * 256 + threadIdx.x;
    int u = id & 511;
    int ch = (id >> 9) & (NCH - 1);
    int b = id >> 14;
    size_t base = ((size_t)b * T_ + (size_t)ch * CL) * U_ + u;
    float h = g_Hin[(b * NCH + ch) * U_ + u];
#pragma unroll 8
    for (int t = 0; t < CL; t++) {
        size_t idx = base + (size_t)t * U_;
        float f = g_F[idx];
        float z = g_Z[idx];
        float o = g_O[idx];
        h = fmaf(f, h - z, z);
        out[idx] = h * o;
    }
}

// ---------------------------------------------------------------------------
extern "C" void kernel_launch(void* const* d_in, const int* in_sizes, int n_in,
                              void* d_out, int out_size)
{
    const float* x    = (const float*)d_in[0];  // [8,2048,512]
    const float* kern = (const float*)d_in[1];  // [2,512,1536]
    const float* bias = (const float*)d_in[2];  // [1536]
    const float* init = (const float*)d_in[3];  // [1,512]
    float* out = (float*)d_out;                 // [8,2048,512]

    cudaFuncSetAttribute(mma_gates, cudaFuncAttributeMaxDynamicSharedMemorySize, SMEM_REQ);

    prep_x<<<(MM * C_) / (256 * 4), 256>>>(x);
    prep_w<<<dim3(NG / 32, KP / 32), dim3(32, 32)>>>(kern);
    mma_gates<<<dim3(NG / BN, MM / BM), 512, SMEM_REQ>>>(bias);
    scan_pass1<<<(B_ * NCH * U_) / 256, 256>>>();
    scan_pass2<<<(B_ * U_) / 512, 512>>>(init);
    scan_pass3<<<(B_ * NCH * U_) / 256, 256>>>(out);
}

// round 8
// speedup vs baseline: 2.6006x; 1.7426x over previous
#include <cuda_runtime.h>
#include <cuda_fp16.h>
#include <stdint.h>

// ---------------------------------------------------------------------------
// Problem constants
// ---------------------------------------------------------------------------
#define B_  8
#define T_  2048
#define C_  512
#define U_  512
#define NG  1536          // 3*U
#define KP  1024          // 2*C (W=2 window)
#define MM  (B_ * T_)     // 16384
#define NITER 32          // KP / BK, single fp16 pass

// GEMM tiling: CTA 256x128, warp 32x64, 512 threads
#define BM 256
#define BN 128
#define BK 32             // fp16 per chunk (64B data/row)
#define LDR 80            // padded smem row bytes (64 data + 16 pad)
#define A_STAGE (BM * LDR)                 // 20480
#define B_STAGE (BN * LDR)                 // 10240
#define STAGE_BYTES (A_STAGE + B_STAGE)    // 30720
#define DEPTH 3
#define SMEM_REQ (DEPTH * STAGE_BYTES)     // 92160

// scan chunking
#define NCH 32
#define CL  (T_ / NCH)    // 64

// ---------------------------------------------------------------------------
// Device scratch (static, no runtime alloc)
// ---------------------------------------------------------------------------
__device__ float g_Z[(size_t)MM * U_];
__device__ float g_F[(size_t)MM * U_];
__device__ float g_O[(size_t)MM * U_];
__device__ __half g_X16[(size_t)MM * C_];
__device__ __half g_WT[(size_t)NG * KP];
__device__ float g_cH[B_ * NCH * U_];
__device__ float g_cP[B_ * NCH * U_];
__device__ float g_Hin[B_ * NCH * U_];

// ---------------------------------------------------------------------------
// Helpers
// ---------------------------------------------------------------------------
__device__ __forceinline__ uint32_t smem_u32(const void* p) {
    uint32_t a;
    asm("{ .reg .u64 t; cvta.to.shared.u64 t, %1; cvt.u32.u64 %0, t; }"
        : "=r"(a) : "l"(p));
    return a;
}

#define CP16P(saddr, gptr, sz) \
    asm volatile("cp.async.cg.shared.global [%0], [%1], 16, %2;" \
                 :: "r"(saddr), "l"(gptr), "r"(sz))
#define CP_COMMIT() asm volatile("cp.async.commit_group;")
#define CP_WAIT1()  asm volatile("cp.async.wait_group 1;")

#define LDSM_X4(r0, r1, r2, r3, addr) \
    asm volatile("ldmatrix.sync.aligned.m8n8.x4.shared.b16 {%0,%1,%2,%3}, [%4];" \
                 : "=r"(r0), "=r"(r1), "=r"(r2), "=r"(r3) : "r"(addr))

#define MMA16816(d, a, b0, b1) \
    asm volatile("mma.sync.aligned.m16n8k16.row.col.f32.f16.f16.f32 " \
                 "{%0,%1,%2,%3}, {%4,%5,%6,%7}, {%8,%9}, {%0,%1,%2,%3};" \
                 : "+f"((d)[0]), "+f"((d)[1]), "+f"((d)[2]), "+f"((d)[3]) \
                 : "r"((a)[0]), "r"((a)[1]), "r"((a)[2]), "r"((a)[3]), \
                   "r"(b0), "r"(b1))

__device__ __forceinline__ float tanh_fast(float x) {
    float r; asm("tanh.approx.f32 %0, %1;" : "=f"(r) : "f"(x)); return r;
}
__device__ __forceinline__ float sig_fast(float x) {
    float e; asm("ex2.approx.f32 %0, %1;" : "=f"(e) : "f"(-x * 1.4426950408889634f));
    float r; asm("rcp.approx.f32 %0, %1;" : "=f"(r) : "f"(1.0f + e)); return r;
}

// ---------------------------------------------------------------------------
// prep_x: fp32 x -> fp16
// ---------------------------------------------------------------------------
__global__ __launch_bounds__(256) void prep_x(const float* __restrict__ x) {
    size_t g = (size_t)blockIdx.x * 256 + threadIdx.x;   // MM*C/4 threads
    float4 v = ((const float4*)x)[g];
    __half2 a; a.x = __float2half(v.x); a.y = __float2half(v.y);
    __half2 b; b.x = __float2half(v.z); b.y = __float2half(v.w);
    ((__half2*)g_X16)[g * 2]     = a;
    ((__half2*)g_X16)[g * 2 + 1] = b;
}

// prep_w: transpose to fp16: kern[k,n] -> WT[n,k]
__global__ void prep_w(const float* __restrict__ kern) {
    __shared__ __half sh[32][33];
    int k = blockIdx.y * 32 + threadIdx.y;
    int n = blockIdx.x * 32 + threadIdx.x;
    sh[threadIdx.y][threadIdx.x] = __float2half(kern[(size_t)k * NG + n]);
    __syncthreads();
    int nn = blockIdx.x * 32 + threadIdx.y;
    int kk = blockIdx.y * 32 + threadIdx.x;
    g_WT[(size_t)nn * KP + kk] = sh[threadIdx.x][threadIdx.y];
}

// ---------------------------------------------------------------------------
// GEMM: gates[16384,1536] = A16[16384,1024] @ WT^T, single fp16 pass.
// A row m, k: source X16[m + w - 1, c]  (w=k/512, c=k%512),
// zero row when (w==0 && m%2048==0). Fused bias + activation epilogue.
// ---------------------------------------------------------------------------
__global__ __launch_bounds__(512) void mma_gates(const float* __restrict__ bias) {
    extern __shared__ char smem[];
    const uint32_t sbase = smem_u32(smem);

    const int tid = threadIdx.x;
    const int wid = tid >> 5;
    const int lane = tid & 31;
    const int n0 = blockIdx.x * BN;
    const int m0 = blockIdx.y * BM;

    const int wm = (wid & 7) * 32;      // warp m offset (8 warps along M)
    const int wn = (wid >> 3) * 64;     // warp n offset (2 warps along N)

    // cp.async: 1536 16B-chunks per stage / 512 threads = 3 per thread
    const int rowq = tid >> 2;          // 0..127
    const int jq   = tid & 3;           // chunk-in-row

#define LOAD_STAGE(cc) do { \
    const int _c = (cc); \
    const int _kb = _c * BK; \
    const uint32_t _st = sbase + (uint32_t)(_c % DEPTH) * STAGE_BYTES; \
    const int _k = _kb + jq * 8; \
    const int _w = _k >> 9; \
    const int _cc2 = _k & 511; \
    _Pragma("unroll") \
    for (int _i = 0; _i < 2; _i++) { \
        int _row = rowq + _i * 128; \
        int _m = m0 + _row; \
        int _r = _m + _w - 1; \
        uint32_t _sz = (_w == 0 && (_m & (T_ - 1)) == 0) ? 0u : 16u; \
        if (_sz == 0u) _r = _m; \
        const void* _gp = g_X16 + (size_t)_r * C_ + _cc2; \
        CP16P(_st + (uint32_t)(_row * LDR + jq * 16), _gp, _sz); \
    } \
    { \
        const void* _gp = g_WT + (size_t)(n0 + rowq) * KP + _kb + jq * 8; \
        CP16P(_st + (uint32_t)(A_STAGE + rowq * LDR + jq * 16), _gp, 16u); \
    } \
    CP_COMMIT(); \
} while (0)

    float acc[2][8][4];
#pragma unroll
    for (int mt = 0; mt < 2; mt++)
#pragma unroll
        for (int nt = 0; nt < 8; nt++)
#pragma unroll
            for (int r = 0; r < 4; r++) acc[mt][nt][r] = 0.0f;

    LOAD_STAGE(0);
    LOAD_STAGE(1);

    // ldmatrix lane address components (fixed per thread)
    const int a_row = lane & 15;             // row within m16 tile
    const int a_chk = lane >> 4;             // 0/1 -> k-half
    const int b_row = (lane & 7) + ((lane >> 4) << 3);  // n row within pair
    const int b_chk = (lane >> 3) & 1;       // k-half select

#pragma unroll 1
    for (int cc = 0; cc < NITER; cc++) {
        CP_WAIT1();
        __syncthreads();
        if (cc + 2 < NITER) {
            LOAD_STAGE(cc + 2);
        } else {
            CP_COMMIT();
        }

        const uint32_t st = sbase + (uint32_t)(cc % DEPTH) * STAGE_BYTES;
        const uint32_t sA = st + (uint32_t)((wm + a_row) * LDR);
        const uint32_t sB = st + (uint32_t)(A_STAGE + (wn + b_row) * LDR);

#pragma unroll
        for (int ks = 0; ks < 2; ks++) {
            uint32_t a[2][4];
            uint32_t b[4][4];
#pragma unroll
            for (int mt = 0; mt < 2; mt++) {
                uint32_t ad = sA + (uint32_t)(mt * 16 * LDR + (a_chk + ks * 2) * 16);
                LDSM_X4(a[mt][0], a[mt][1], a[mt][2], a[mt][3], ad);
            }
#pragma unroll
            for (int p = 0; p < 4; p++) {
                uint32_t bd = sB + (uint32_t)(p * 16 * LDR + (b_chk + ks * 2) * 16);
                LDSM_X4(b[p][0], b[p][1], b[p][2], b[p][3], bd);
            }
#pragma unroll
            for (int mt = 0; mt < 2; mt++)
#pragma unroll
                for (int p = 0; p < 4; p++) {
                    MMA16816(acc[mt][2 * p],     a[mt], b[p][0], b[p][1]);
                    MMA16816(acc[mt][2 * p + 1], a[mt], b[p][2], b[p][3]);
                }
        }
    }

    // ---- epilogue: bias + activation + store, straight from registers ----
    const int ng = n0 + wn;                   // warp n base (global)
    const int gate = ng >> 9;                 // 0:z 1:f 2:o
    float* dst = (gate == 0) ? g_Z : ((gate == 1) ? g_F : g_O);
    const int colw = (ng & 511) + (lane & 3) * 2;

    float bs0[8], bs1[8];
#pragma unroll
    for (int nt = 0; nt < 8; nt++) {
        bs0[nt] = __ldg(bias + ng + (lane & 3) * 2 + nt * 8);
        bs1[nt] = __ldg(bias + ng + (lane & 3) * 2 + nt * 8 + 1);
    }

#pragma unroll
    for (int mt = 0; mt < 2; mt++) {
        int row = m0 + wm + mt * 16 + (lane >> 2);
        float* p0 = dst + (size_t)row * U_;
        float* p1 = dst + (size_t)(row + 8) * U_;
#pragma unroll
        for (int nt = 0; nt < 8; nt++) {
            int col = colw + nt * 8;
            float g0 = acc[mt][nt][0] + bs0[nt];
            float g1 = acc[mt][nt][1] + bs1[nt];
            float g2 = acc[mt][nt][2] + bs0[nt];
            float g3 = acc[mt][nt][3] + bs1[nt];
            float2 v0, v1;
            if (gate == 0) {
                v0.x = tanh_fast(g0); v0.y = tanh_fast(g1);
                v1.x = tanh_fast(g2); v1.y = tanh_fast(g3);
            } else {
                v0.x = sig_fast(g0); v0.y = sig_fast(g1);
                v1.x = sig_fast(g2); v1.y = sig_fast(g3);
            }
            *(float2*)(p0 + col) = v0;
            *(float2*)(p1 + col) = v1;
        }
    }
}

// ---------------------------------------------------------------------------
// Chunked fo-pool scan (h affine in h_in: h = P*h_in + H) — scalar
// ---------------------------------------------------------------------------
__global__ __launch_bounds__(256) void scan_pass1() {
    int id = blockIdx.x * 256 + threadIdx.x;       // B*NCH*U = 131072
    int u = id & 511;
    int ch = (id >> 9) & (NCH - 1);
    int b = id >> 14;
    size_t base = ((size_t)b * T_ + (size_t)ch * CL) * U_ + u;
    float h = 0.0f, P = 1.0f;
#pragma unroll 8
    for (int t = 0; t < CL; t++) {
        float f = g_F[base + (size_t)t * U_];
        float z = g_Z[base + (size_t)t * U_];
        h = fmaf(f, h - z, z);
        P *= f;
    }
    int o = (b * NCH + ch) * U_ + u;
    g_cH[o] = h;
    g_cP[o] = P;
}

__global__ __launch_bounds__(512) void scan_pass2(const float* __restrict__ init) {
    int id = blockIdx.x * 512 + threadIdx.x;       // 4096 = B*U
    int u = id & 511;
    int b = id >> 9;
    float h = init[u];
#pragma unroll
    for (int c = 0; c < NCH; c++) {
        int o = (b * NCH + c) * U_ + u;
        g_Hin[o] = h;
        h = fmaf(g_cP[o], h, g_cH[o]);
    }
}

__global__ __launch_bounds__(256) void scan_pass3(float* __restrict__ out) {
    int id = blockIdx.x * 256 + threadIdx.x;
    int u = id & 511;
    int ch = (id >> 9) & (NCH - 1);
    int b = id >> 14;
    size_t base = ((size_t)b * T_ + (size_t)ch * CL) * U_ + u;
    float h = g_Hin[(b * NCH + ch) * U_ + u];
#pragma unroll 8
    for (int t = 0; t < CL; t++) {
        size_t idx = base + (size_t)t * U_;
        float f = g_F[idx];
        float z = g_Z[idx];
        float o = g_O[idx];
        h = fmaf(f, h - z, z);
        out[idx] = h * o;
    }
}

// ---------------------------------------------------------------------------
extern "C" void kernel_launch(void* const* d_in, const int* in_sizes, int n_in,
                              void* d_out, int out_size)
{
    const float* x    = (const float*)d_in[0];  // [8,2048,512]
    const float* kern = (const float*)d_in[1];  // [2,512,1536]
    const float* bias = (const float*)d_in[2];  // [1536]
    const float* init = (const float*)d_in[3];  // [1,512]
    float* out = (float*)d_out;                 // [8,2048,512]

    cudaFuncSetAttribute(mma_gates, cudaFuncAttributeMaxDynamicSharedMemorySize, SMEM_REQ);

    prep_x<<<(MM * C_) / (256 * 4), 256>>>(x);
    prep_w<<<dim3(NG / 32, KP / 32), dim3(32, 32)>>>(kern);
    mma_gates<<<dim3(NG / BN, MM / BM), 512, SMEM_REQ>>>(bias);
    scan_pass1<<<(B_ * NCH * U_) / 256, 256>>>();
    scan_pass2<<<(B_ * U_) / 512, 512>>>(init);
    scan_pass3<<<(B_ * NCH * U_) / 256, 256>>>(out);
}

// round 9
// speedup vs baseline: 2.6572x; 1.0218x over previous
#include <cuda_runtime.h>
#include <cuda_fp16.h>
#include <stdint.h>

// ---------------------------------------------------------------------------
// Problem constants
// ---------------------------------------------------------------------------
#define B_  8
#define T_  2048
#define C_  512
#define U_  512
#define NG  1536          // 3*U
#define KP  1024          // 2*C (W=2 window)
#define MM  (B_ * T_)     // 16384
#define NITER 32          // KP / BK, single fp16 pass

// GEMM tiling: CTA 256x128, warp 32x64, 512 threads
#define BM 256
#define BN 128
#define BK 32             // fp16 per chunk (64B data/row)
#define LDR 80            // padded smem row bytes (64 data + 16 pad)
#define A_STAGE (BM * LDR)                 // 20480
#define B_STAGE (BN * LDR)                 // 10240
#define STAGE_BYTES (A_STAGE + B_STAGE)    // 30720
#define DEPTH 3
#define SMEM_REQ (DEPTH * STAGE_BYTES)     // 92160

// scan chunking
#define NCH 32
#define CL  (T_ / NCH)    // 64

// ---------------------------------------------------------------------------
// Device scratch (static, no runtime alloc). Gates stored as fp16.
// ---------------------------------------------------------------------------
__device__ __half g_Zh[(size_t)MM * U_];
__device__ __half g_Fh[(size_t)MM * U_];
__device__ __half g_Oh[(size_t)MM * U_];
__device__ __half g_X16[(size_t)MM * C_];
__device__ __half g_WT[(size_t)NG * KP];
__device__ float g_cH[B_ * NCH * U_];
__device__ float g_cP[B_ * NCH * U_];
__device__ float g_Hin[B_ * NCH * U_];

// ---------------------------------------------------------------------------
// Helpers
// ---------------------------------------------------------------------------
__device__ __forceinline__ uint32_t smem_u32(const void* p) {
    uint32_t a;
    asm("{ .reg .u64 t; cvta.to.shared.u64 t, %1; cvt.u32.u64 %0, t; }"
        : "=r"(a) : "l"(p));
    return a;
}

#define CP16P(saddr, gptr, sz) \
    asm volatile("cp.async.cg.shared.global [%0], [%1], 16, %2;" \
                 :: "r"(saddr), "l"(gptr), "r"(sz))
#define CP_COMMIT() asm volatile("cp.async.commit_group;")
#define CP_WAIT1()  asm volatile("cp.async.wait_group 1;")

#define LDSM_X4(r0, r1, r2, r3, addr) \
    asm volatile("ldmatrix.sync.aligned.m8n8.x4.shared.b16 {%0,%1,%2,%3}, [%4];" \
                 : "=r"(r0), "=r"(r1), "=r"(r2), "=r"(r3) : "r"(addr))

#define MMA16816(d, a, b0, b1) \
    asm volatile("mma.sync.aligned.m16n8k16.row.col.f32.f16.f16.f32 " \
                 "{%0,%1,%2,%3}, {%4,%5,%6,%7}, {%8,%9}, {%0,%1,%2,%3};" \
                 : "+f"((d)[0]), "+f"((d)[1]), "+f"((d)[2]), "+f"((d)[3]) \
                 : "r"((a)[0]), "r"((a)[1]), "r"((a)[2]), "r"((a)[3]), \
                   "r"(b0), "r"(b1))

__device__ __forceinline__ float tanh_fast(float x) {
    float r; asm("tanh.approx.f32 %0, %1;" : "=f"(r) : "f"(x)); return r;
}
__device__ __forceinline__ float sig_fast(float x) {
    float e; asm("ex2.approx.f32 %0, %1;" : "=f"(e) : "f"(-x * 1.4426950408889634f));
    float r; asm("rcp.approx.f32 %0, %1;" : "=f"(r) : "f"(1.0f + e)); return r;
}

// ---------------------------------------------------------------------------
// prep_x: fp32 x -> fp16
// ---------------------------------------------------------------------------
__global__ __launch_bounds__(256) void prep_x(const float* __restrict__ x) {
    size_t g = (size_t)blockIdx.x * 256 + threadIdx.x;   // MM*C/4 threads
    float4 v = ((const float4*)x)[g];
    __half2 a; a.x = __float2half(v.x); a.y = __float2half(v.y);
    __half2 b; b.x = __float2half(v.z); b.y = __float2half(v.w);
    ((__half2*)g_X16)[g * 2]     = a;
    ((__half2*)g_X16)[g * 2 + 1] = b;
}

// prep_w: transpose to fp16: kern[k,n] -> WT[n,k]
__global__ void prep_w(const float* __restrict__ kern) {
    __shared__ __half sh[32][33];
    int k = blockIdx.y * 32 + threadIdx.y;
    int n = blockIdx.x * 32 + threadIdx.x;
    sh[threadIdx.y][threadIdx.x] = __float2half(kern[(size_t)k * NG + n]);
    __syncthreads();
    int nn = blockIdx.x * 32 + threadIdx.y;
    int kk = blockIdx.y * 32 + threadIdx.x;
    g_WT[(size_t)nn * KP + kk] = sh[threadIdx.x][threadIdx.y];
}

// ---------------------------------------------------------------------------
// GEMM: gates[16384,1536] = A16[16384,1024] @ WT^T, single fp16 pass.
// A row m, k: source X16[m + w - 1, c]  (w=k/512, c=k%512),
// zero row when (w==0 && m%2048==0). Fused bias + activation epilogue,
// gates stored fp16.
// ---------------------------------------------------------------------------
__global__ __launch_bounds__(512) void mma_gates(const float* __restrict__ bias) {
    extern __shared__ char smem[];
    const uint32_t sbase = smem_u32(smem);

    const int tid = threadIdx.x;
    const int wid = tid >> 5;
    const int lane = tid & 31;
    const int n0 = blockIdx.x * BN;
    const int m0 = blockIdx.y * BM;

    const int wm = (wid & 7) * 32;      // warp m offset (8 warps along M)
    const int wn = (wid >> 3) * 64;     // warp n offset (2 warps along N)

    // cp.async: 1536 16B-chunks per stage / 512 threads = 3 per thread
    const int rowq = tid >> 2;          // 0..127
    const int jq   = tid & 3;           // chunk-in-row

#define LOAD_STAGE(cc) do { \
    const int _c = (cc); \
    const int _kb = _c * BK; \
    const uint32_t _st = sbase + (uint32_t)(_c % DEPTH) * STAGE_BYTES; \
    const int _k = _kb + jq * 8; \
    const int _w = _k >> 9; \
    const int _cc2 = _k & 511; \
    _Pragma("unroll") \
    for (int _i = 0; _i < 2; _i++) { \
        int _row = rowq + _i * 128; \
        int _m = m0 + _row; \
        int _r = _m + _w - 1; \
        uint32_t _sz = (_w == 0 && (_m & (T_ - 1)) == 0) ? 0u : 16u; \
        if (_sz == 0u) _r = _m; \
        const void* _gp = g_X16 + (size_t)_r * C_ + _cc2; \
        CP16P(_st + (uint32_t)(_row * LDR + jq * 16), _gp, _sz); \
    } \
    { \
        const void* _gp = g_WT + (size_t)(n0 + rowq) * KP + _kb + jq * 8; \
        CP16P(_st + (uint32_t)(A_STAGE + rowq * LDR + jq * 16), _gp, 16u); \
    } \
    CP_COMMIT(); \
} while (0)

    float acc[2][8][4];
#pragma unroll
    for (int mt = 0; mt < 2; mt++)
#pragma unroll
        for (int nt = 0; nt < 8; nt++)
#pragma unroll
            for (int r = 0; r < 4; r++) acc[mt][nt][r] = 0.0f;

    LOAD_STAGE(0);
    LOAD_STAGE(1);

    // ldmatrix lane address components (fixed per thread)
    const int a_row = lane & 15;             // row within m16 tile
    const int a_chk = lane >> 4;             // 0/1 -> k-half
    const int b_row = (lane & 7) + ((lane >> 4) << 3);  // n row within pair
    const int b_chk = (lane >> 3) & 1;       // k-half select

#pragma unroll 1
    for (int cc = 0; cc < NITER; cc++) {
        CP_WAIT1();
        __syncthreads();
        if (cc + 2 < NITER) {
            LOAD_STAGE(cc + 2);
        } else {
            CP_COMMIT();
        }

        const uint32_t st = sbase + (uint32_t)(cc % DEPTH) * STAGE_BYTES;
        const uint32_t sA = st + (uint32_t)((wm + a_row) * LDR);
        const uint32_t sB = st + (uint32_t)(A_STAGE + (wn + b_row) * LDR);

#pragma unroll
        for (int ks = 0; ks < 2; ks++) {
            uint32_t a[2][4];
            uint32_t b[4][4];
#pragma unroll
            for (int mt = 0; mt < 2; mt++) {
                uint32_t ad = sA + (uint32_t)(mt * 16 * LDR + (a_chk + ks * 2) * 16);
                LDSM_X4(a[mt][0], a[mt][1], a[mt][2], a[mt][3], ad);
            }
#pragma unroll
            for (int p = 0; p < 4; p++) {
                uint32_t bd = sB + (uint32_t)(p * 16 * LDR + (b_chk + ks * 2) * 16);
                LDSM_X4(b[p][0], b[p][1], b[p][2], b[p][3], bd);
            }
#pragma unroll
            for (int mt = 0; mt < 2; mt++)
#pragma unroll
                for (int p = 0; p < 4; p++) {
                    MMA16816(acc[mt][2 * p],     a[mt], b[p][0], b[p][1]);
                    MMA16816(acc[mt][2 * p + 1], a[mt], b[p][2], b[p][3]);
                }
        }
    }

    // ---- epilogue: bias + activation + fp16 store, straight from registers --
    const int ng = n0 + wn;                   // warp n base (global)
    const int gate = ng >> 9;                 // 0:z 1:f 2:o
    __half* dst = (gate == 0) ? g_Zh : ((gate == 1) ? g_Fh : g_Oh);
    const int colw = (ng & 511) + (lane & 3) * 2;

    float bs0[8], bs1[8];
#pragma unroll
    for (int nt = 0; nt < 8; nt++) {
        bs0[nt] = __ldg(bias + ng + (lane & 3) * 2 + nt * 8);
        bs1[nt] = __ldg(bias + ng + (lane & 3) * 2 + nt * 8 + 1);
    }

#pragma unroll
    for (int mt = 0; mt < 2; mt++) {
        int row = m0 + wm + mt * 16 + (lane >> 2);
        __half* p0 = dst + (size_t)row * U_;
        __half* p1 = dst + (size_t)(row + 8) * U_;
#pragma unroll
        for (int nt = 0; nt < 8; nt++) {
            int col = colw + nt * 8;
            float g0 = acc[mt][nt][0] + bs0[nt];
            float g1 = acc[mt][nt][1] + bs1[nt];
            float g2 = acc[mt][nt][2] + bs0[nt];
            float g3 = acc[mt][nt][3] + bs1[nt];
            __half2 v0, v1;
            if (gate == 0) {
                v0.x = __float2half(tanh_fast(g0)); v0.y = __float2half(tanh_fast(g1));
                v1.x = __float2half(tanh_fast(g2)); v1.y = __float2half(tanh_fast(g3));
            } else {
                v0.x = __float2half(sig_fast(g0)); v0.y = __float2half(sig_fast(g1));
                v1.x = __float2half(sig_fast(g2)); v1.y = __float2half(sig_fast(g3));
            }
            *(__half2*)(p0 + col) = v0;
            *(__half2*)(p1 + col) = v1;
        }
    }
}

// ---------------------------------------------------------------------------
// Chunked fo-pool scan (h affine in h_in: h = P*h_in + H) — fp16 gate loads
// ---------------------------------------------------------------------------
__global__ __launch_bounds__(256) void scan_pass1() {
    int id = blockIdx.x * 256 + threadIdx.x;       // B*NCH*U = 131072
    int u = id & 511;
    int ch = (id >> 9) & (NCH - 1);
    int b = id >> 14;
    size_t base = ((size_t)b * T_ + (size_t)ch * CL) * U_ + u;
    float h = 0.0f, P = 1.0f;
#pragma unroll 8
    for (int t = 0; t < CL; t++) {
        float f = __half2float(g_Fh[base + (size_t)t * U_]);
        float z = __half2float(g_Zh[base + (size_t)t * U_]);
        h = fmaf(f, h - z, z);
        P *= f;
    }
    int o = (b * NCH + ch) * U_ + u;
    g_cH[o] = h;
    g_cP[o] = P;
}

__global__ __launch_bounds__(512) void scan_pass2(const float* __restrict__ init) {
    int id = blockIdx.x * 512 + threadIdx.x;       // 4096 = B*U
    int u = id & 511;
    int b = id >> 9;
    float h = init[u];
#pragma unroll
    for (int c = 0; c < NCH; c++) {
        int o = (b * NCH + c) * U_ + u;
        g_Hin[o] = h;
        h = fmaf(g_cP[o], h, g_cH[o]);
    }
}

__global__ __launch_bounds__(256) void scan_pass3(float* __restrict__ out) {
    int id = blockIdx.x * 256 + threadIdx.x;
    int u = id & 511;
    int ch = (id >> 9) & (NCH - 1);
    int b = id >> 14;
    size_t base = ((size_t)b * T_ + (size_t)ch * CL) * U_ + u;
    float h = g_Hin[(b * NCH + ch) * U_ + u];
#pragma unroll 8
    for (int t = 0; t < CL; t++) {
        size_t idx = base + (size_t)t * U_;
        float f = __half2float(g_Fh[idx]);
        float z = __half2float(g_Zh[idx]);
        float o = __half2float(g_Oh[idx]);
        h = fmaf(f, h - z, z);
        out[idx] = h * o;
    }
}

// ---------------------------------------------------------------------------
extern "C" void kernel_launch(void* const* d_in, const int* in_sizes, int n_in,
                              void* d_out, int out_size)
{
    const float* x    = (const float*)d_in[0];  // [8,2048,512]
    const float* kern = (const float*)d_in[1];  // [2,512,1536]
    const float* bias = (const float*)d_in[2];  // [1536]
    const float* init = (const float*)d_in[3];  // [1,512]
    float* out = (float*)d_out;                 // [8,2048,512]

    cudaFuncSetAttribute(mma_gates, cudaFuncAttributeMaxDynamicSharedMemorySize, SMEM_REQ);

    prep_x<<<(MM * C_) / (256 * 4), 256>>>(x);
    prep_w<<<dim3(NG / 32, KP / 32), dim3(32, 32)>>>(kern);
    mma_gates<<<dim3(NG / BN, MM / BM), 512, SMEM_REQ>>>(bias);
    scan_pass1<<<(B_ * NCH * U_) / 256, 256>>>();
    scan_pass2<<<(B_ * U_) / 512, 512>>>(init);
    scan_pass3<<<(B_ * NCH * U_) / 256, 256>>>(out);
}

// round 10
// speedup vs baseline: 3.0829x; 1.1602x over previous
#include <cuda_runtime.h>
#include <cuda_fp16.h>
#include <stdint.h>

// ---------------------------------------------------------------------------
// Problem constants
// ---------------------------------------------------------------------------
#define B_  8
#define T_  2048
#define C_  512
#define U_  512
#define NG  1536          // 3*U
#define KP  1024          // 2*C (W=2 window)
#define MM  (B_ * T_)     // 16384
#define NITER 32          // KP / BK, single fp16 pass

// GEMM tiling: CTA 128x128, warp 32x64 (8 warps: 4 along M x 2 along N)
#define BM 128
#define BN 128
#define BK 32             // fp16 per chunk (64B data/row)
#define LDR 80            // padded smem row bytes (64 data + 16 pad)
#define A_STAGE (BM * LDR)                 // 10240
#define B_STAGE (BN * LDR)                 // 10240
#define STAGE_BYTES (A_STAGE + B_STAGE)    // 20480
#define DEPTH 3
#define SMEM_REQ (DEPTH * STAGE_BYTES)     // 61440 -> 2 CTAs/SM

// scan chunking
#define NCH 32
#define CL  (T_ / NCH)    // 64

// ---------------------------------------------------------------------------
// Device scratch (static, no runtime alloc). Gates stored as fp16.
// ---------------------------------------------------------------------------
__device__ __half g_Zh[(size_t)MM * U_];
__device__ __half g_Fh[(size_t)MM * U_];
__device__ __half g_Oh[(size_t)MM * U_];
__device__ __half g_X16[(size_t)MM * C_];
__device__ __half g_WT[(size_t)NG * KP];
__device__ float g_cH[B_ * NCH * U_];
__device__ float g_cP[B_ * NCH * U_];
__device__ float g_Hin[B_ * NCH * U_];

// ---------------------------------------------------------------------------
// Helpers
// ---------------------------------------------------------------------------
__device__ __forceinline__ uint32_t smem_u32(const void* p) {
    uint32_t a;
    asm("{ .reg .u64 t; cvta.to.shared.u64 t, %1; cvt.u32.u64 %0, t; }"
        : "=r"(a) : "l"(p));
    return a;
}

#define CP16P(saddr, gptr, sz) \
    asm volatile("cp.async.cg.shared.global [%0], [%1], 16, %2;" \
                 :: "r"(saddr), "l"(gptr), "r"(sz))
#define CP_COMMIT() asm volatile("cp.async.commit_group;")
#define CP_WAIT1()  asm volatile("cp.async.wait_group 1;")

#define LDSM_X4(r0, r1, r2, r3, addr) \
    asm volatile("ldmatrix.sync.aligned.m8n8.x4.shared.b16 {%0,%1,%2,%3}, [%4];" \
                 : "=r"(r0), "=r"(r1), "=r"(r2), "=r"(r3) : "r"(addr))

#define MMA16816(d, a, b0, b1) \
    asm volatile("mma.sync.aligned.m16n8k16.row.col.f32.f16.f16.f32 " \
                 "{%0,%1,%2,%3}, {%4,%5,%6,%7}, {%8,%9}, {%0,%1,%2,%3};" \
                 : "+f"((d)[0]), "+f"((d)[1]), "+f"((d)[2]), "+f"((d)[3]) \
                 : "r"((a)[0]), "r"((a)[1]), "r"((a)[2]), "r"((a)[3]), \
                   "r"(b0), "r"(b1))

__device__ __forceinline__ float tanh_fast(float x) {
    float r; asm("tanh.approx.f32 %0, %1;" : "=f"(r) : "f"(x)); return r;
}
__device__ __forceinline__ float sig_fast(float x) {
    float e; asm("ex2.approx.f32 %0, %1;" : "=f"(e) : "f"(-x * 1.4426950408889634f));
    float r; asm("rcp.approx.f32 %0, %1;" : "=f"(r) : "f"(1.0f + e)); return r;
}

// ---------------------------------------------------------------------------
// prep_x: fp32 x -> fp16
// ---------------------------------------------------------------------------
__global__ __launch_bounds__(256) void prep_x(const float* __restrict__ x) {
    size_t g = (size_t)blockIdx.x * 256 + threadIdx.x;   // MM*C/4 threads
    float4 v = ((const float4*)x)[g];
    __half2 a; a.x = __float2half(v.x); a.y = __float2half(v.y);
    __half2 b; b.x = __float2half(v.z); b.y = __float2half(v.w);
    ((__half2*)g_X16)[g * 2]     = a;
    ((__half2*)g_X16)[g * 2 + 1] = b;
}

// prep_w: transpose to fp16: kern[k,n] -> WT[n,k]
__global__ void prep_w(const float* __restrict__ kern) {
    __shared__ __half sh[32][33];
    int k = blockIdx.y * 32 + threadIdx.y;
    int n = blockIdx.x * 32 + threadIdx.x;
    sh[threadIdx.y][threadIdx.x] = __float2half(kern[(size_t)k * NG + n]);
    __syncthreads();
    int nn = blockIdx.x * 32 + threadIdx.y;
    int kk = blockIdx.y * 32 + threadIdx.x;
    g_WT[(size_t)nn * KP + kk] = sh[threadIdx.x][threadIdx.y];
}

// ---------------------------------------------------------------------------
// GEMM: gates[16384,1536] = A16[16384,1024] @ WT^T, single fp16 pass.
// A row m, k: source X16[m + w - 1, c]  (w=k/512, c=k%512),
// zero row when (w==0 && m%2048==0). Fused bias + activation epilogue,
// gates stored fp16. CTA 128x128, 2 CTAs/SM.
// ---------------------------------------------------------------------------
__global__ __launch_bounds__(256, 2) void mma_gates(const float* __restrict__ bias) {
    extern __shared__ char smem[];
    const uint32_t sbase = smem_u32(smem);

    const int tid = threadIdx.x;
    const int wid = tid >> 5;
    const int lane = tid & 31;
    const int n0 = blockIdx.x * BN;
    const int m0 = blockIdx.y * BM;

    const int wm = (wid & 3) * 32;      // warp m offset (4 warps along M)
    const int wn = (wid >> 2) * 64;     // warp n offset (2 warps along N)

    // cp.async: 1024 16B-chunks per stage / 256 threads = 4 per thread
    const int rowq = tid >> 2;          // 0..63
    const int jq   = tid & 3;           // chunk-in-row

#define LOAD_STAGE(cc) do { \
    const int _c = (cc); \
    const int _kb = _c * BK; \
    const uint32_t _st = sbase + (uint32_t)(_c % DEPTH) * STAGE_BYTES; \
    const int _k = _kb + jq * 8; \
    const int _w = _k >> 9; \
    const int _cc2 = _k & 511; \
    _Pragma("unroll") \
    for (int _i = 0; _i < 2; _i++) { \
        int _row = rowq + _i * 64; \
        int _m = m0 + _row; \
        int _r = _m + _w - 1; \
        uint32_t _sz = (_w == 0 && (_m & (T_ - 1)) == 0) ? 0u : 16u; \
        if (_sz == 0u) _r = _m; \
        const void* _gp = g_X16 + (size_t)_r * C_ + _cc2; \
        CP16P(_st + (uint32_t)(_row * LDR + jq * 16), _gp, _sz); \
    } \
    _Pragma("unroll") \
    for (int _i = 0; _i < 2; _i++) { \
        int _row = rowq + _i * 64; \
        const void* _gp = g_WT + (size_t)(n0 + _row) * KP + _kb + jq * 8; \
        CP16P(_st + (uint32_t)(A_STAGE + _row * LDR + jq * 16), _gp, 16u); \
    } \
    CP_COMMIT(); \
} while (0)

    float acc[2][8][4];
#pragma unroll
    for (int mt = 0; mt < 2; mt++)
#pragma unroll
        for (int nt = 0; nt < 8; nt++)
#pragma unroll
            for (int r = 0; r < 4; r++) acc[mt][nt][r] = 0.0f;

    LOAD_STAGE(0);
    LOAD_STAGE(1);

    // ldmatrix lane address components (fixed per thread)
    const int a_row = lane & 15;             // row within m16 tile
    const int a_chk = lane >> 4;             // 0/1 -> k-half
    const int b_row = (lane & 7) + ((lane >> 4) << 3);  // n row within pair
    const int b_chk = (lane >> 3) & 1;       // k-half select

#pragma unroll 1
    for (int cc = 0; cc < NITER; cc++) {
        CP_WAIT1();
        __syncthreads();
        if (cc + 2 < NITER) {
            LOAD_STAGE(cc + 2);
        } else {
            CP_COMMIT();
        }

        const uint32_t st = sbase + (uint32_t)(cc % DEPTH) * STAGE_BYTES;
        const uint32_t sA = st + (uint32_t)((wm + a_row) * LDR);
        const uint32_t sB = st + (uint32_t)(A_STAGE + (wn + b_row) * LDR);

#pragma unroll
        for (int ks = 0; ks < 2; ks++) {
            uint32_t a[2][4];
            uint32_t b[4][4];
#pragma unroll
            for (int mt = 0; mt < 2; mt++) {
                uint32_t ad = sA + (uint32_t)(mt * 16 * LDR + (a_chk + ks * 2) * 16);
                LDSM_X4(a[mt][0], a[mt][1], a[mt][2], a[mt][3], ad);
            }
#pragma unroll
            for (int p = 0; p < 4; p++) {
                uint32_t bd = sB + (uint32_t)(p * 16 * LDR + (b_chk + ks * 2) * 16);
                LDSM_X4(b[p][0], b[p][1], b[p][2], b[p][3], bd);
            }
#pragma unroll
            for (int mt = 0; mt < 2; mt++)
#pragma unroll
                for (int p = 0; p < 4; p++) {
                    MMA16816(acc[mt][2 * p],     a[mt], b[p][0], b[p][1]);
                    MMA16816(acc[mt][2 * p + 1], a[mt], b[p][2], b[p][3]);
                }
        }
    }

    // ---- epilogue: bias + activation + fp16 store, straight from registers --
    const int ng = n0 + wn;                   // warp n base (global)
    const int gate = ng >> 9;                 // 0:z 1:f 2:o
    __half* dst = (gate == 0) ? g_Zh : ((gate == 1) ? g_Fh : g_Oh);
    const int colw = (ng & 511) + (lane & 3) * 2;

    float bs0[8], bs1[8];
#pragma unroll
    for (int nt = 0; nt < 8; nt++) {
        bs0[nt] = __ldg(bias + ng + (lane & 3) * 2 + nt * 8);
        bs1[nt] = __ldg(bias + ng + (lane & 3) * 2 + nt * 8 + 1);
    }

#pragma unroll
    for (int mt = 0; mt < 2; mt++) {
        int row = m0 + wm + mt * 16 + (lane >> 2);
        __half* p0 = dst + (size_t)row * U_;
        __half* p1 = dst + (size_t)(row + 8) * U_;
#pragma unroll
        for (int nt = 0; nt < 8; nt++) {
            int col = colw + nt * 8;
            float g0 = acc[mt][nt][0] + bs0[nt];
            float g1 = acc[mt][nt][1] + bs1[nt];
            float g2 = acc[mt][nt][2] + bs0[nt];
            float g3 = acc[mt][nt][3] + bs1[nt];
            __half2 v0, v1;
            if (gate == 0) {
                v0.x = __float2half(tanh_fast(g0)); v0.y = __float2half(tanh_fast(g1));
                v1.x = __float2half(tanh_fast(g2)); v1.y = __float2half(tanh_fast(g3));
            } else {
                v0.x = __float2half(sig_fast(g0)); v0.y = __float2half(sig_fast(g1));
                v1.x = __float2half(sig_fast(g2)); v1.y = __float2half(sig_fast(g3));
            }
            *(__half2*)(p0 + col) = v0;
            *(__half2*)(p1 + col) = v1;
        }
    }
}

// ---------------------------------------------------------------------------
// Chunked fo-pool scan (h affine in h_in: h = P*h_in + H) — fp16 gate loads
// ---------------------------------------------------------------------------
__global__ __launch_bounds__(256) void scan_pass1() {
    int id = blockIdx.x * 256 + threadIdx.x;       // B*NCH*U = 131072
    int u = id & 511;
    int ch = (id >> 9) & (NCH - 1);
    int b = id >> 14;
    size_t base = ((size_t)b * T_ + (size_t)ch * CL) * U_ + u;
    float h = 0.0f, P = 1.0f;
#pragma unroll 8
    for (int t = 0; t < CL; t++) {
        float f = __half2float(g_Fh[base + (size_t)t * U_]);
        float z = __half2float(g_Zh[base + (size_t)t * U_]);
        h = fmaf(f, h - z, z);
        P *= f;
    }
    int o = (b * NCH + ch) * U_ + u;
    g_cH[o] = h;
    g_cP[o] = P;
}

__global__ __launch_bounds__(512) void scan_pass2(const float* __restrict__ init) {
    int id = blockIdx.x * 512 + threadIdx.x;       // 4096 = B*U
    int u = id & 511;
    int b = id >> 9;
    float h = init[u];
#pragma unroll
    for (int c = 0; c < NCH; c++) {
        int o = (b * NCH + c) * U_ + u;
        g_Hin[o] = h;
        h = fmaf(g_cP[o], h, g_cH[o]);
    }
}

__global__ __launch_bounds__(256) void scan_pass3(float* __restrict__ out) {
    int id = blockIdx.x * 256 + threadIdx.x;
    int u = id & 511;
    int ch = (id >> 9) & (NCH - 1);
    int b = id >> 14;
    size_t base = ((size_t)b * T_ + (size_t)ch * CL) * U_ + u;
    float h = g_Hin[(b * NCH + ch) * U_ + u];
#pragma unroll 8
    for (int t = 0; t < CL; t++) {
        size_t idx = base + (size_t)t * U_;
        float f = __half2float(g_Fh[idx]);
        float z = __half2float(g_Zh[idx]);
        float o = __half2float(g_Oh[idx]);
        h = fmaf(f, h - z, z);
        out[idx] = h * o;
    }
}

// ---------------------------------------------------------------------------
extern "C" void kernel_launch(void* const* d_in, const int* in_sizes, int n_in,
                              void* d_out, int out_size)
{
    const float* x    = (const float*)d_in[0];  // [8,2048,512]
    const float* kern = (const float*)d_in[1];  // [2,512,1536]
    const float* bias = (const float*)d_in[2];  // [1536]
    const float* init = (const float*)d_in[3];  // [1,512]
    float* out = (float*)d_out;                 // [8,2048,512]

    cudaFuncSetAttribute(mma_gates, cudaFuncAttributeMaxDynamicSharedMemorySize, SMEM_REQ);

    prep_x<<<(MM * C_) / (256 * 4), 256>>>(x);
    prep_w<<<dim3(NG / 32, KP / 32), dim3(32, 32)>>>(kern);
    mma_gates<<<dim3(NG / BN, MM / BM), 256, SMEM_REQ>>>(bias);
    scan_pass1<<<(B_ * NCH * U_) / 256, 256>>>();
    scan_pass2<<<(B_ * U_) / 512, 512>>>(init);
    scan_pass3<<<(B_ * NCH * U_) / 256, 256>>>(out);
}

// round 11
// speedup vs baseline: 3.2512x; 1.0546x over previous
#include <cuda_runtime.h>
#include <cuda_fp16.h>
#include <stdint.h>

// ---------------------------------------------------------------------------
// Problem constants
// ---------------------------------------------------------------------------
#define B_  8
#define T_  2048
#define C_  512
#define U_  512
#define NG  1536          // 3*U
#define KP  1024          // 2*C (W=2 window)
#define MM  (B_ * T_)     // 16384
#define NITER 16          // KP / BK, single fp16 pass

// GEMM tiling: CTA 128x128, warp 32x64 (8 warps: 4 along M x 2 along N)
#define BM 128
#define BN 128
#define BK 64             // fp16 per chunk (128B data/row)
#define LDR 144           // padded smem row bytes (128 data + 16 pad)
#define A_STAGE (BM * LDR)                 // 18432
#define B_STAGE (BN * LDR)                 // 18432
#define STAGE_BYTES (A_STAGE + B_STAGE)    // 36864
#define DEPTH 3
#define SMEM_REQ (DEPTH * STAGE_BYTES)     // 110592 -> 2 CTAs/SM

// scan chunking
#define NCH 64
#define CL  (T_ / NCH)    // 32

// merged prep grid split
#define NXBLK ((MM * C_) / (4 * 1024))     // 2048 blocks for x-convert

// ---------------------------------------------------------------------------
// Device scratch (static, no runtime alloc). Gates stored as fp16.
// ---------------------------------------------------------------------------
__device__ __half g_Zh[(size_t)MM * U_];
__device__ __half g_Fh[(size_t)MM * U_];
__device__ __half g_Oh[(size_t)MM * U_];
__device__ __half g_X16[(size_t)MM * C_];
__device__ __half g_WT[(size_t)NG * KP];
__device__ float g_cH[B_ * NCH * U_];
__device__ float g_cP[B_ * NCH * U_];
__device__ float g_Hin[B_ * NCH * U_];

// ---------------------------------------------------------------------------
// Helpers
// ---------------------------------------------------------------------------
__device__ __forceinline__ uint32_t smem_u32(const void* p) {
    uint32_t a;
    asm("{ .reg .u64 t; cvta.to.shared.u64 t, %1; cvt.u32.u64 %0, t; }"
        : "=r"(a) : "l"(p));
    return a;
}

#define CP16P(saddr, gptr, sz) \
    asm volatile("cp.async.cg.shared.global [%0], [%1], 16, %2;" \
                 :: "r"(saddr), "l"(gptr), "r"(sz))
#define CP_COMMIT() asm volatile("cp.async.commit_group;")
#define CP_WAIT1()  asm volatile("cp.async.wait_group 1;")

#define LDSM_X4(r0, r1, r2, r3, addr) \
    asm volatile("ldmatrix.sync.aligned.m8n8.x4.shared.b16 {%0,%1,%2,%3}, [%4];" \
                 : "=r"(r0), "=r"(r1), "=r"(r2), "=r"(r3) : "r"(addr))

#define MMA16816(d, a, b0, b1) \
    asm volatile("mma.sync.aligned.m16n8k16.row.col.f32.f16.f16.f32 " \
                 "{%0,%1,%2,%3}, {%4,%5,%6,%7}, {%8,%9}, {%0,%1,%2,%3};" \
                 : "+f"((d)[0]), "+f"((d)[1]), "+f"((d)[2]), "+f"((d)[3]) \
                 : "r"((a)[0]), "r"((a)[1]), "r"((a)[2]), "r"((a)[3]), \
                   "r"(b0), "r"(b1))

__device__ __forceinline__ float tanh_fast(float x) {
    float r; asm("tanh.approx.f32 %0, %1;" : "=f"(r) : "f"(x)); return r;
}
__device__ __forceinline__ float sig_fast(float x) {
    float e; asm("ex2.approx.f32 %0, %1;" : "=f"(e) : "f"(-x * 1.4426950408889634f));
    float r; asm("rcp.approx.f32 %0, %1;" : "=f"(r) : "f"(1.0f + e)); return r;
}

// ---------------------------------------------------------------------------
// prep_all: blocks [0,NXBLK): fp32 x -> fp16; rest: transpose W -> fp16 WT
// ---------------------------------------------------------------------------
__global__ __launch_bounds__(1024) void prep_all(const float* __restrict__ x,
                                                 const float* __restrict__ kern) {
    __shared__ __half sh[32][33];
    const int blk = blockIdx.x;
    if (blk < NXBLK) {
        size_t g = (size_t)blk * 1024 + threadIdx.x;   // MM*C/4 elements
        float4 v = ((const float4*)x)[g];
        __half2 a; a.x = __float2half(v.x); a.y = __float2half(v.y);
        __half2 b; b.x = __float2half(v.z); b.y = __float2half(v.w);
        ((__half2*)g_X16)[g * 2]     = a;
        ((__half2*)g_X16)[g * 2 + 1] = b;
    } else {
        const int wb = blk - NXBLK;          // 0..1535 = (NG/32)*(KP/32)
        const int bx = wb % (NG / 32);       // n-tile
        const int by = wb / (NG / 32);       // k-tile
        const int tx = threadIdx.x & 31;
        const int ty = threadIdx.x >> 5;
        int k = by * 32 + ty;
        int n = bx * 32 + tx;
        sh[ty][tx] = __float2half(kern[(size_t)k * NG + n]);
        __syncthreads();
        int nn = bx * 32 + ty;
        int kk = by * 32 + tx;
        g_WT[(size_t)nn * KP + kk] = sh[tx][ty];
    }
}

// ---------------------------------------------------------------------------
// GEMM: gates[16384,1536] = A16[16384,1024] @ WT^T, single fp16 pass.
// A row m, k: source X16[m + w - 1, c]  (w=k/512, c=k%512),
// zero row when (w==0 && m%2048==0). Fused bias + activation epilogue,
// gates stored fp16. CTA 128x128, BK=64, 2 CTAs/SM.
// ---------------------------------------------------------------------------
__global__ __launch_bounds__(256, 2) void mma_gates(const float* __restrict__ bias) {
    extern __shared__ char smem[];
    const uint32_t sbase = smem_u32(smem);

    const int tid = threadIdx.x;
    const int wid = tid >> 5;
    const int lane = tid & 31;
    const int n0 = blockIdx.x * BN;
    const int m0 = blockIdx.y * BM;

    const int wm = (wid & 3) * 32;      // warp m offset (4 warps along M)
    const int wn = (wid >> 2) * 64;     // warp n offset (2 warps along N)

    // cp.async: 2048 16B-chunks per stage / 256 threads = 8 per thread
    const int rowq = tid >> 3;          // 0..31
    const int jq   = tid & 7;           // chunk-in-row (8 per 128B row)

#define LOAD_STAGE(cc) do { \
    const int _c = (cc); \
    const int _kb = _c * BK; \
    const uint32_t _st = sbase + (uint32_t)(_c % DEPTH) * STAGE_BYTES; \
    const int _k = _kb + jq * 8; \
    const int _w = _k >> 9; \
    const int _cc2 = _k & 511; \
    _Pragma("unroll") \
    for (int _i = 0; _i < 4; _i++) { \
        int _row = rowq + _i * 32; \
        int _m = m0 + _row; \
        int _r = _m + _w - 1; \
        uint32_t _sz = (_w == 0 && (_m & (T_ - 1)) == 0) ? 0u : 16u; \
        if (_sz == 0u) _r = _m; \
        const void* _gp = g_X16 + (size_t)_r * C_ + _cc2; \
        CP16P(_st + (uint32_t)(_row * LDR + jq * 16), _gp, _sz); \
    } \
    _Pragma("unroll") \
    for (int _i = 0; _i < 4; _i++) { \
        int _row = rowq + _i * 32; \
        const void* _gp = g_WT + (size_t)(n0 + _row) * KP + _kb + jq * 8; \
        CP16P(_st + (uint32_t)(A_STAGE + _row * LDR + jq * 16), _gp, 16u); \
    } \
    CP_COMMIT(); \
} while (0)

    float acc[2][8][4];
#pragma unroll
    for (int mt = 0; mt < 2; mt++)
#pragma unroll
        for (int nt = 0; nt < 8; nt++)
#pragma unroll
            for (int r = 0; r < 4; r++) acc[mt][nt][r] = 0.0f;

    LOAD_STAGE(0);
    LOAD_STAGE(1);

    // ldmatrix lane address components (fixed per thread)
    const int a_row = lane & 15;             // row within m16 tile
    const int a_chk = lane >> 4;             // 0/1 -> k-half
    const int b_row = (lane & 7) + ((lane >> 4) << 3);  // n row within pair
    const int b_chk = (lane >> 3) & 1;       // k-half select

#pragma unroll 1
    for (int cc = 0; cc < NITER; cc++) {
        CP_WAIT1();
        __syncthreads();
        if (cc + 2 < NITER) {
            LOAD_STAGE(cc + 2);
        } else {
            CP_COMMIT();
        }

        const uint32_t st = sbase + (uint32_t)(cc % DEPTH) * STAGE_BYTES;
        const uint32_t sA = st + (uint32_t)((wm + a_row) * LDR);
        const uint32_t sB = st + (uint32_t)(A_STAGE + (wn + b_row) * LDR);

#pragma unroll
        for (int ks = 0; ks < 4; ks++) {
            uint32_t a[2][4];
            uint32_t b[4][4];
#pragma unroll
            for (int mt = 0; mt < 2; mt++) {
                uint32_t ad = sA + (uint32_t)(mt * 16 * LDR + (a_chk + ks * 2) * 16);
                LDSM_X4(a[mt][0], a[mt][1], a[mt][2], a[mt][3], ad);
            }
#pragma unroll
            for (int p = 0; p < 4; p++) {
                uint32_t bd = sB + (uint32_t)(p * 16 * LDR + (b_chk + ks * 2) * 16);
                LDSM_X4(b[p][0], b[p][1], b[p][2], b[p][3], bd);
            }
#pragma unroll
            for (int mt = 0; mt < 2; mt++)
#pragma unroll
                for (int p = 0; p < 4; p++) {
                    MMA16816(acc[mt][2 * p],     a[mt], b[p][0], b[p][1]);
                    MMA16816(acc[mt][2 * p + 1], a[mt], b[p][2], b[p][3]);
                }
        }
    }

    // ---- epilogue: bias + activation + fp16 store, straight from registers --
    const int ng = n0 + wn;                   // warp n base (global)
    const int gate = ng >> 9;                 // 0:z 1:f 2:o
    __half* dst = (gate == 0) ? g_Zh : ((gate == 1) ? g_Fh : g_Oh);
    const int colw = (ng & 511) + (lane & 3) * 2;

    float bs0[8], bs1[8];
#pragma unroll
    for (int nt = 0; nt < 8; nt++) {
        bs0[nt] = __ldg(bias + ng + (lane & 3) * 2 + nt * 8);
        bs1[nt] = __ldg(bias + ng + (lane & 3) * 2 + nt * 8 + 1);
    }

#pragma unroll
    for (int mt = 0; mt < 2; mt++) {
        int row = m0 + wm + mt * 16 + (lane >> 2);
        __half* p0 = dst + (size_t)row * U_;
        __half* p1 = dst + (size_t)(row + 8) * U_;
#pragma unroll
        for (int nt = 0; nt < 8; nt++) {
            int col = colw + nt * 8;
            float g0 = acc[mt][nt][0] + bs0[nt];
            float g1 = acc[mt][nt][1] + bs1[nt];
            float g2 = acc[mt][nt][2] + bs0[nt];
            float g3 = acc[mt][nt][3] + bs1[nt];
            __half2 v0, v1;
            if (gate == 0) {
                v0.x = __float2half(tanh_fast(g0)); v0.y = __float2half(tanh_fast(g1));
                v1.x = __float2half(tanh_fast(g2)); v1.y = __float2half(tanh_fast(g3));
            } else {
                v0.x = __float2half(sig_fast(g0)); v0.y = __float2half(sig_fast(g1));
                v1.x = __float2half(sig_fast(g2)); v1.y = __float2half(sig_fast(g3));
            }
            *(__half2*)(p0 + col) = v0;
            *(__half2*)(p1 + col) = v1;
        }
    }
}

// ---------------------------------------------------------------------------
// Chunked fo-pool scan (h affine in h_in: h = P*h_in + H) — fp16 gate loads
// ---------------------------------------------------------------------------
__global__ __launch_bounds__(256) void scan_pass1() {
    int id = blockIdx.x * 256 + threadIdx.x;       // B*NCH*U = 262144
    int u = id & 511;
    int ch = (id >> 9) & (NCH - 1);
    int b = id >> 15;
    size_t base = ((size_t)b * T_ + (size_t)ch * CL) * U_ + u;
    float h = 0.0f, P = 1.0f;
#pragma unroll 8
    for (int t = 0; t < CL; t++) {
        float f = __half2float(g_Fh[base + (size_t)t * U_]);
        float z = __half2float(g_Zh[base + (size_t)t * U_]);
        h = fmaf(f, h - z, z);
        P *= f;
    }
    int o = (b * NCH + ch) * U_ + u;
    g_cH[o] = h;
    g_cP[o] = P;
}

__global__ __launch_bounds__(512) void scan_pass2(const float* __restrict__ init) {
    int id = blockIdx.x * 512 + threadIdx.x;       // 4096 = B*U
    int u = id & 511;
    int b = id >> 9;
    float h = init[u];
#pragma unroll
    for (int c = 0; c < NCH; c++) {
        int o = (b * NCH + c) * U_ + u;
        g_Hin[o] = h;
        h = fmaf(g_cP[o], h, g_cH[o]);
    }
}

__global__ __launch_bounds__(256) void scan_pass3(float* __restrict__ out) {
    int id = blockIdx.x * 256 + threadIdx.x;       // 262144
    int u = id & 511;
    int ch = (id >> 9) & (NCH - 1);
    int b = id >> 15;
    size_t base = ((size_t)b * T_ + (size_t)ch * CL) * U_ + u;
    float h = g_Hin[(b * NCH + ch) * U_ + u];
#pragma unroll 8
    for (int t = 0; t < CL; t++) {
        size_t idx = base + (size_t)t * U_;
        float f = __half2float(g_Fh[idx]);
        float z = __half2float(g_Zh[idx]);
        float o = __half2float(g_Oh[idx]);
        h = fmaf(f, h - z, z);
        out[idx] = h * o;
    }
}

// ---------------------------------------------------------------------------
extern "C" void kernel_launch(void* const* d_in, const int* in_sizes, int n_in,
                              void* d_out, int out_size)
{
    const float* x    = (const float*)d_in[0];  // [8,2048,512]
    const float* kern = (const float*)d_in[1];  // [2,512,1536]
    const float* bias = (const float*)d_in[2];  // [1536]
    const float* init = (const float*)d_in[3];  // [1,512]
    float* out = (float*)d_out;                 // [8,2048,512]

    cudaFuncSetAttribute(mma_gates, cudaFuncAttributeMaxDynamicSharedMemorySize, SMEM_REQ);

    prep_all<<<NXBLK + (NG / 32) * (KP / 32), 1024>>>(x, kern);
    mma_gates<<<dim3(NG / BN, MM / BM), 256, SMEM_REQ>>>(bias);
    scan_pass1<<<(B_ * NCH * U_) / 256, 256>>>();
    scan_pass2<<<(B_ * U_) / 512, 512>>>(init);
    scan_pass3<<<(B_ * NCH * U_) / 256, 256>>>(out);
}

// round 12
// speedup vs baseline: 3.5251x; 1.0843x over previous
#include <cuda_runtime.h>
#include <cuda_fp16.h>
#include <stdint.h>

// ---------------------------------------------------------------------------
// Problem constants
// ---------------------------------------------------------------------------
#define B_  8
#define T_  2048
#define C_  512
#define U_  512
#define NG  1536          // 3*U
#define KP  1024          // 2*C (W=2 window)
#define MM  (B_ * T_)     // 16384
#define NITER 16          // KP / BK, single fp16 pass

// GEMM tiling: CTA 128x128, warp 32x64 (8 warps: 4 along M x 2 along N)
#define BM 128
#define BN 128
#define BK 64             // fp16 per chunk (128B data/row)
#define LDR 144           // padded smem row bytes (128 data + 16 pad)
#define A_STAGE (BM * LDR)                 // 18432
#define B_STAGE (BN * LDR)                 // 18432
#define STAGE_BYTES (A_STAGE + B_STAGE)    // 36864
#define DEPTH 3
#define SMEM_REQ (DEPTH * STAGE_BYTES)     // 110592 -> 2 CTAs/SM

// scan chunking
#define NCH 64
#define CL  (T_ / NCH)    // 32

// merged prep grid split
#define NXBLK ((MM * C_) / (4 * 1024))     // 2048 blocks for x-convert

// ---------------------------------------------------------------------------
// Device scratch (static, no runtime alloc). Gates stored as fp16.
// ---------------------------------------------------------------------------
__device__ __half g_Zh[(size_t)MM * U_];
__device__ __half g_Fh[(size_t)MM * U_];
__device__ __half g_Oh[(size_t)MM * U_];
__device__ __half g_X16[(size_t)MM * C_];
__device__ __half g_WT[(size_t)NG * KP];
__device__ float g_cH[B_ * NCH * U_];
__device__ float g_cP[B_ * NCH * U_];
__device__ float g_Hin[B_ * NCH * U_];

// ---------------------------------------------------------------------------
// Helpers
// ---------------------------------------------------------------------------
__device__ __forceinline__ uint32_t smem_u32(const void* p) {
    uint32_t a;
    asm("{ .reg .u64 t; cvta.to.shared.u64 t, %1; cvt.u32.u64 %0, t; }"
        : "=r"(a) : "l"(p));
    return a;
}

#define CP16P(saddr, gptr, sz) \
    asm volatile("cp.async.cg.shared.global [%0], [%1], 16, %2;" \
                 :: "r"(saddr), "l"(gptr), "r"(sz))
#define CP_COMMIT() asm volatile("cp.async.commit_group;")
#define CP_WAIT1()  asm volatile("cp.async.wait_group 1;")

#define LDSM_X4(r0, r1, r2, r3, addr) \
    asm volatile("ldmatrix.sync.aligned.m8n8.x4.shared.b16 {%0,%1,%2,%3}, [%4];" \
                 : "=r"(r0), "=r"(r1), "=r"(r2), "=r"(r3) : "r"(addr))

#define MMA16816(d, a, b0, b1) \
    asm volatile("mma.sync.aligned.m16n8k16.row.col.f32.f16.f16.f32 " \
                 "{%0,%1,%2,%3}, {%4,%5,%6,%7}, {%8,%9}, {%0,%1,%2,%3};" \
                 : "+f"((d)[0]), "+f"((d)[1]), "+f"((d)[2]), "+f"((d)[3]) \
                 : "r"((a)[0]), "r"((a)[1]), "r"((a)[2]), "r"((a)[3]), \
                   "r"(b0), "r"(b1))

__device__ __forceinline__ float tanh_fast(float x) {
    float r; asm("tanh.approx.f32 %0, %1;" : "=f"(r) : "f"(x)); return r;
}
__device__ __forceinline__ float sig_fast(float x) {
    float e; asm("ex2.approx.f32 %0, %1;" : "=f"(e) : "f"(-x * 1.4426950408889634f));
    float r; asm("rcp.approx.f32 %0, %1;" : "=f"(r) : "f"(1.0f + e)); return r;
}

// ---------------------------------------------------------------------------
// prep_all: blocks [0,NXBLK): fp32 x -> fp16; rest: transpose W -> fp16 WT
// ---------------------------------------------------------------------------
__global__ __launch_bounds__(1024) void prep_all(const float* __restrict__ x,
                                                 const float* __restrict__ kern) {
    __shared__ __half sh[32][33];
    const int blk = blockIdx.x;
    if (blk < NXBLK) {
        size_t g = (size_t)blk * 1024 + threadIdx.x;   // MM*C/4 elements
        float4 v = ((const float4*)x)[g];
        __half2 a; a.x = __float2half(v.x); a.y = __float2half(v.y);
        __half2 b; b.x = __float2half(v.z); b.y = __float2half(v.w);
        ((__half2*)g_X16)[g * 2]     = a;
        ((__half2*)g_X16)[g * 2 + 1] = b;
    } else {
        const int wb = blk - NXBLK;          // 0..1535 = (NG/32)*(KP/32)
        const int bx = wb % (NG / 32);       // n-tile
        const int by = wb / (NG / 32);       // k-tile
        const int tx = threadIdx.x & 31;
        const int ty = threadIdx.x >> 5;
        int k = by * 32 + ty;
        int n = bx * 32 + tx;
        sh[ty][tx] = __float2half(kern[(size_t)k * NG + n]);
        __syncthreads();
        int nn = bx * 32 + ty;
        int kk = by * 32 + tx;
        g_WT[(size_t)nn * KP + kk] = sh[tx][ty];
    }
}

// ---------------------------------------------------------------------------
// GEMM: gates[16384,1536] = A16[16384,1024] @ WT^T, single fp16 pass.
// A row m, k: source X16[m + w - 1, c]  (w=k/512, c=k%512),
// zero row when (w==0 && m%2048==0). Fused bias + activation epilogue,
// gates stored fp16. CTA 128x128, BK=64, 2 CTAs/SM.
// ---------------------------------------------------------------------------
__global__ __launch_bounds__(256, 2) void mma_gates(const float* __restrict__ bias) {
    extern __shared__ char smem[];
    const uint32_t sbase = smem_u32(smem);

    const int tid = threadIdx.x;
    const int wid = tid >> 5;
    const int lane = tid & 31;
    const int n0 = blockIdx.x * BN;
    const int m0 = blockIdx.y * BM;

    const int wm = (wid & 3) * 32;      // warp m offset (4 warps along M)
    const int wn = (wid >> 2) * 64;     // warp n offset (2 warps along N)

    // cp.async: 2048 16B-chunks per stage / 256 threads = 8 per thread
    const int rowq = tid >> 3;          // 0..31
    const int jq   = tid & 7;           // chunk-in-row (8 per 128B row)

#define LOAD_STAGE(cc) do { \
    const int _c = (cc); \
    const int _kb = _c * BK; \
    const uint32_t _st = sbase + (uint32_t)(_c % DEPTH) * STAGE_BYTES; \
    const int _k = _kb + jq * 8; \
    const int _w = _k >> 9; \
    const int _cc2 = _k & 511; \
    _Pragma("unroll") \
    for (int _i = 0; _i < 4; _i++) { \
        int _row = rowq + _i * 32; \
        int _m = m0 + _row; \
        int _r = _m + _w - 1; \
        uint32_t _sz = (_w == 0 && (_m & (T_ - 1)) == 0) ? 0u : 16u; \
        if (_sz == 0u) _r = _m; \
        const void* _gp = g_X16 + (size_t)_r * C_ + _cc2; \
        CP16P(_st + (uint32_t)(_row * LDR + jq * 16), _gp, _sz); \
    } \
    _Pragma("unroll") \
    for (int _i = 0; _i < 4; _i++) { \
        int _row = rowq + _i * 32; \
        const void* _gp = g_WT + (size_t)(n0 + _row) * KP + _kb + jq * 8; \
        CP16P(_st + (uint32_t)(A_STAGE + _row * LDR + jq * 16), _gp, 16u); \
    } \
    CP_COMMIT(); \
} while (0)

    float acc[2][8][4];
#pragma unroll
    for (int mt = 0; mt < 2; mt++)
#pragma unroll
        for (int nt = 0; nt < 8; nt++)
#pragma unroll
            for (int r = 0; r < 4; r++) acc[mt][nt][r] = 0.0f;

    LOAD_STAGE(0);
    LOAD_STAGE(1);

    // ldmatrix lane address components (fixed per thread)
    const int a_row = lane & 15;             // row within m16 tile
    const int a_chk = lane >> 4;             // 0/1 -> k-half
    const int b_row = (lane & 7) + ((lane >> 4) << 3);  // n row within pair
    const int b_chk = (lane >> 3) & 1;       // k-half select

#pragma unroll 1
    for (int cc = 0; cc < NITER; cc++) {
        CP_WAIT1();
        __syncthreads();
        if (cc + 2 < NITER) {
            LOAD_STAGE(cc + 2);
        } else {
            CP_COMMIT();
        }

        const uint32_t st = sbase + (uint32_t)(cc % DEPTH) * STAGE_BYTES;
        const uint32_t sA = st + (uint32_t)((wm + a_row) * LDR);
        const uint32_t sB = st + (uint32_t)(A_STAGE + (wn + b_row) * LDR);

#pragma unroll
        for (int ks = 0; ks < 4; ks++) {
            uint32_t a[2][4];
            uint32_t b[4][4];
#pragma unroll
            for (int mt = 0; mt < 2; mt++) {
                uint32_t ad = sA + (uint32_t)(mt * 16 * LDR + (a_chk + ks * 2) * 16);
                LDSM_X4(a[mt][0], a[mt][1], a[mt][2], a[mt][3], ad);
            }
#pragma unroll
            for (int p = 0; p < 4; p++) {
                uint32_t bd = sB + (uint32_t)(p * 16 * LDR + (b_chk + ks * 2) * 16);
                LDSM_X4(b[p][0], b[p][1], b[p][2], b[p][3], bd);
            }
#pragma unroll
            for (int mt = 0; mt < 2; mt++)
#pragma unroll
                for (int p = 0; p < 4; p++) {
                    MMA16816(acc[mt][2 * p],     a[mt], b[p][0], b[p][1]);
                    MMA16816(acc[mt][2 * p + 1], a[mt], b[p][2], b[p][3]);
                }
        }
    }

    // ---- epilogue: bias + activation + fp16 store, straight from registers --
    const int ng = n0 + wn;                   // warp n base (global)
    const int gate = ng >> 9;                 // 0:z 1:f 2:o
    __half* dst = (gate == 0) ? g_Zh : ((gate == 1) ? g_Fh : g_Oh);
    const int colw = (ng & 511) + (lane & 3) * 2;

    float bs0[8], bs1[8];
#pragma unroll
    for (int nt = 0; nt < 8; nt++) {
        bs0[nt] = __ldg(bias + ng + (lane & 3) * 2 + nt * 8);
        bs1[nt] = __ldg(bias + ng + (lane & 3) * 2 + nt * 8 + 1);
    }

#pragma unroll
    for (int mt = 0; mt < 2; mt++) {
        int row = m0 + wm + mt * 16 + (lane >> 2);
        __half* p0 = dst + (size_t)row * U_;
        __half* p1 = dst + (size_t)(row + 8) * U_;
#pragma unroll
        for (int nt = 0; nt < 8; nt++) {
            int col = colw + nt * 8;
            float g0 = acc[mt][nt][0] + bs0[nt];
            float g1 = acc[mt][nt][1] + bs1[nt];
            float g2 = acc[mt][nt][2] + bs0[nt];
            float g3 = acc[mt][nt][3] + bs1[nt];
            __half2 v0, v1;
            if (gate == 0) {
                v0.x = __float2half(tanh_fast(g0)); v0.y = __float2half(tanh_fast(g1));
                v1.x = __float2half(tanh_fast(g2)); v1.y = __float2half(tanh_fast(g3));
            } else {
                v0.x = __float2half(sig_fast(g0)); v0.y = __float2half(sig_fast(g1));
                v1.x = __float2half(sig_fast(g2)); v1.y = __float2half(sig_fast(g3));
            }
            *(__half2*)(p0 + col) = v0;
            *(__half2*)(p1 + col) = v1;
        }
    }
}

// ---------------------------------------------------------------------------
// Chunked fo-pool scan (h affine in h_in: h = P*h_in + H) — fp16 gate loads
// ---------------------------------------------------------------------------
__global__ __launch_bounds__(256) void scan_pass1() {
    int id = blockIdx.x * 256 + threadIdx.x;       // B*NCH*U = 262144
    int u = id & 511;
    int ch = (id >> 9) & (NCH - 1);
    int b = id >> 15;
    size_t base = ((size_t)b * T_ + (size_t)ch * CL) * U_ + u;
    float h = 0.0f, P = 1.0f;
#pragma unroll 8
    for (int t = 0; t < CL; t++) {
        float f = __half2float(g_Fh[base + (size_t)t * U_]);
        float z = __half2float(g_Zh[base + (size_t)t * U_]);
        h = fmaf(f, h - z, z);
        P *= f;
    }
    int o = (b * NCH + ch) * U_ + u;
    g_cH[o] = h;
    g_cP[o] = P;
}

// pass2: register-preload all 64 (P,H) pairs, then run the fma chain from regs.
// 128 threads/block, 32 blocks; no launch_bounds cap so ~140 regs are fine.
__global__ void scan_pass2(const float* __restrict__ init) {
    int id = blockIdx.x * 128 + threadIdx.x;       // 4096 = B*U
    int u = id & 511;
    int b = id >> 9;
    const int o0 = b * NCH * U_ + u;

    float P[NCH], H[NCH];
#pragma unroll
    for (int c = 0; c < NCH; c++) {
        P[c] = g_cP[o0 + c * U_];
        H[c] = g_cH[o0 + c * U_];
    }

    float h = init[u];
#pragma unroll
    for (int c = 0; c < NCH; c++) {
        g_Hin[o0 + c * U_] = h;
        h = fmaf(P[c], h, H[c]);
    }
}

__global__ __launch_bounds__(256) void scan_pass3(float* __restrict__ out) {
    int id = blockIdx.x * 256 + threadIdx.x;       // 262144
    int u = id & 511;
    int ch = (id >> 9) & (NCH - 1);
    int b = id >> 15;
    size_t base = ((size_t)b * T_ + (size_t)ch * CL) * U_ + u;
    float h = g_Hin[(b * NCH + ch) * U_ + u];
#pragma unroll 8
    for (int t = 0; t < CL; t++) {
        size_t idx = base + (size_t)t * U_;
        float f = __half2float(g_Fh[idx]);
        float z = __half2float(g_Zh[idx]);
        float o = __half2float(g_Oh[idx]);
        h = fmaf(f, h - z, z);
        out[idx] = h * o;
    }
}

// ---------------------------------------------------------------------------
extern "C" void kernel_launch(void* const* d_in, const int* in_sizes, int n_in,
                              void* d_out, int out_size)
{
    const float* x    = (const float*)d_in[0];  // [8,2048,512]
    const float* kern = (const float*)d_in[1];  // [2,512,1536]
    const float* bias = (const float*)d_in[2];  // [1536]
    const float* init = (const float*)d_in[3];  // [1,512]
    float* out = (float*)d_out;                 // [8,2048,512]

    cudaFuncSetAttribute(mma_gates, cudaFuncAttributeMaxDynamicSharedMemorySize, SMEM_REQ);

    prep_all<<<NXBLK + (NG / 32) * (KP / 32), 1024>>>(x, kern);
    mma_gates<<<dim3(NG / BN, MM / BM), 256, SMEM_REQ>>>(bias);
    scan_pass1<<<(B_ * NCH * U_) / 256, 256>>>();
    scan_pass2<<<(B_ * U_) / 128, 128>>>(init);
    scan_pass3<<<(B_ * NCH * U_) / 256, 256>>>(out);
}